// round 2
// baseline (speedup 1.0000x reference)
#include <cuda_runtime.h>
#include <math.h>

#define BT   8192      // B*T tokens
#define Dm   1024
#define HIDm 2048
#define Tlen 2048
#define Bb   4

// ---- static scratch (no allocations allowed) ----
__device__ float g_h[BT * Dm];        // h, later reused as attn_out
__device__ float g_q[BT * Dm];        // q, later reused as h2
__device__ float g_k[BT * Dm];
__device__ float g_v[BT * Dm];
__device__ float g_beta[BT];
__device__ float g_m1[BT * HIDm];     // gate -> silu(gate)*up
__device__ float g_m2[BT * HIDm];     // up

// ---------------- block reduction helper (256 threads) ----------------
__device__ __forceinline__ float block_sum_256(float v) {
    __shared__ float sh[8];
    int lane = threadIdx.x & 31, wid = threadIdx.x >> 5;
#pragma unroll
    for (int o = 16; o; o >>= 1) v += __shfl_xor_sync(0xffffffffu, v, o);
    if (lane == 0) sh[wid] = v;
    __syncthreads();
    if (wid == 0) {
        float t = (lane < 8) ? sh[lane] : 0.f;
#pragma unroll
        for (int o = 4; o; o >>= 1) t += __shfl_xor_sync(0xffffffffu, t, o);
        if (lane == 0) sh[0] = t;
    }
    __syncthreads();
    return sh[0];
}

// ---------------- rmsnorm: one block per row (D=1024, 256 thr) ----------------
__global__ __launch_bounds__(256) void rmsnorm_k(const float* __restrict__ x,
                                                 const float* __restrict__ w,
                                                 float* __restrict__ out) {
    int row = blockIdx.x;
    const float* xr = x + (size_t)row * Dm;
    float* orow = out + (size_t)row * Dm;
    float v[4];
    float ss = 0.f;
#pragma unroll
    for (int i = 0; i < 4; i++) {
        v[i] = xr[i * 256 + threadIdx.x];
        ss += v[i] * v[i];
    }
    float tot = block_sum_256(ss);
    float scale = rsqrtf(tot * (1.0f / Dm) + 1e-6f);
#pragma unroll
    for (int i = 0; i < 4; i++) {
        int c = i * 256 + threadIdx.x;
        orow[c] = v[i] * scale * w[c];
    }
}

// ---------------- k row L2-normalize in place ----------------
__global__ __launch_bounds__(256) void knorm_k(float* __restrict__ k) {
    int row = blockIdx.x;
    float* kr = k + (size_t)row * Dm;
    float v[4];
    float ss = 0.f;
#pragma unroll
    for (int i = 0; i < 4; i++) {
        v[i] = kr[i * 256 + threadIdx.x];
        ss += v[i] * v[i];
    }
    float tot = block_sum_256(ss);
    float scale = 1.f / fmaxf(sqrtf(tot), 1e-12f);
#pragma unroll
    for (int i = 0; i < 4; i++) kr[i * 256 + threadIdx.x] = v[i] * scale;
}

// ---------------- beta = sigmoid(h . beta_w + beta_b), warp per row ----------------
__global__ __launch_bounds__(256) void beta_k(const float* __restrict__ h,
                                              const float* __restrict__ bw,
                                              const float* __restrict__ bb,
                                              float* __restrict__ beta) {
    int row = blockIdx.x * 8 + (threadIdx.x >> 5);
    int lane = threadIdx.x & 31;
    const float* hr = h + (size_t)row * Dm;
    float s = 0.f;
#pragma unroll
    for (int m = 0; m < 32; m++) s += hr[m * 32 + lane] * bw[m * 32 + lane];
#pragma unroll
    for (int o = 16; o; o >>= 1) s += __shfl_xor_sync(0xffffffffu, s, o);
    if (lane == 0) beta[row] = 1.f / (1.f + expf(-(s + bb[0])));
}

// ---------------- per-channel EMA scan over T (in place on v) ----------------
__global__ __launch_bounds__(256) void ema_k(float* __restrict__ v,
                                             const float* __restrict__ alpha_logit) {
    int d = blockIdx.x * 256 + threadIdx.x;
    int b = blockIdx.y;
    float a = 1.f / (1.f + expf(-alpha_logit[d]));
    float om = 1.f - a;
    float prev = 0.f;
    size_t idx = (size_t)b * Tlen * Dm + d;
    for (int t = 0; t < Tlen; t++, idx += Dm) {
        float cur = a * v[idx] + om * prev;
        v[idx] = cur;
        prev = cur;
    }
}

// ---------------- delta-rule scan ----------------
// grid (D/32, B), 512 threads. Warp w owns rows rowbase+2w, rowbase+2w+1.
// Lane l holds columns l+32m (m=0..31) of each row in registers.
__global__ __launch_bounds__(512, 1) void delta_k(const float* __restrict__ q,
                                                  const float* __restrict__ k,
                                                  const float* __restrict__ v,
                                                  const float* __restrict__ beta,
                                                  float* __restrict__ o) {
    __shared__ float ksm[Dm];
    __shared__ float qsm[Dm];
    __shared__ float vsm[32];
    __shared__ float osm[32];
    __shared__ float bsm;

    int b = blockIdx.y;
    int rowbase = blockIdx.x * 32;
    int tid = threadIdx.x;
    int lane = tid & 31, w = tid >> 5;

    const float* qb = q + (size_t)b * Tlen * Dm;
    const float* kb = k + (size_t)b * Tlen * Dm;
    const float* vb = v + (size_t)b * Tlen * Dm;
    const float* betab = beta + (size_t)b * Tlen;
    float* ob = o + (size_t)b * Tlen * Dm;

    float S0[32], S1[32];
#pragma unroll
    for (int m = 0; m < 32; m++) { S0[m] = 0.f; S1[m] = 0.f; }

    for (int t = 0; t < Tlen; t++) {
        int base = t * Dm;
        ksm[tid]       = kb[base + tid];
        ksm[tid + 512] = kb[base + tid + 512];
        qsm[tid]       = qb[base + tid];
        qsm[tid + 512] = qb[base + tid + 512];
        if (tid < 32) vsm[tid] = vb[base + rowbase + tid];
        if (tid == 0) bsm = betab[t];
        __syncthreads();

        float kk[32];
        float d0 = 0.f, d1 = 0.f;
#pragma unroll
        for (int m = 0; m < 32; m++) {
            kk[m] = ksm[m * 32 + lane];
            d0 += S0[m] * kk[m];
            d1 += S1[m] * kk[m];
        }
#pragma unroll
        for (int off = 16; off; off >>= 1) {
            d0 += __shfl_xor_sync(0xffffffffu, d0, off);
            d1 += __shfl_xor_sync(0xffffffffu, d1, off);
        }
        float bt = bsm;
        float e0 = bt * (vsm[2 * w]     - d0);
        float e1 = bt * (vsm[2 * w + 1] - d1);

        float o0 = 0.f, o1 = 0.f;
#pragma unroll
        for (int m = 0; m < 32; m++) {
            float qq = qsm[m * 32 + lane];
            S0[m] += e0 * kk[m];
            o0 += S0[m] * qq;
            S1[m] += e1 * kk[m];
            o1 += S1[m] * qq;
        }
#pragma unroll
        for (int off = 16; off; off >>= 1) {
            o0 += __shfl_xor_sync(0xffffffffu, o0, off);
            o1 += __shfl_xor_sync(0xffffffffu, o1, off);
        }
        if (lane == 0) { osm[2 * w] = o0; osm[2 * w + 1] = o1; }
        __syncthreads();
        if (tid < 32) ob[base + rowbase + tid] = osm[tid];
    }
}

// ---------------- tiled fp32 GEMM: C[M,N] = A[M,K] @ B[K,N] (row-major) ----------------
// EPI 0: C = acc ; EPI 1: C = Res + acc ; EPI 2: C += acc
template <int EPI>
__global__ __launch_bounds__(256) void sgemm(const float* __restrict__ A,
                                             const float* __restrict__ B,
                                             float* __restrict__ C,
                                             const float* __restrict__ Res,
                                             int M, int N, int K) {
    __shared__ float As[16][128];
    __shared__ float Bs[16][128];
    const int tid = threadIdx.x;
    const int bm = blockIdx.y, bn = blockIdx.x;
    const int tm = (tid / 16) * 8, tn = (tid % 16) * 8;

    float acc[8][8];
#pragma unroll
    for (int i = 0; i < 8; i++)
#pragma unroll
        for (int j = 0; j < 8; j++) acc[i][j] = 0.f;

    const int a_r0 = tid >> 2;           // 0..63
    const int a_c0 = (tid & 3) * 4;      // 0,4,8,12
    const int b_r0 = tid >> 5;           // 0..7
    const int b_c0 = (tid & 31) * 4;     // 0..124

    const float* Ab = A + (size_t)(bm * 128) * K;
    const float* Bb_ = B + bn * 128;

    for (int kt = 0; kt < K; kt += 16) {
        float4 av0 = *(const float4*)&Ab[(size_t)a_r0 * K + kt + a_c0];
        float4 av1 = *(const float4*)&Ab[(size_t)(64 + a_r0) * K + kt + a_c0];
        float4 bv0 = *(const float4*)&Bb_[(size_t)(kt + b_r0) * N + b_c0];
        float4 bv1 = *(const float4*)&Bb_[(size_t)(kt + 8 + b_r0) * N + b_c0];
        __syncthreads();
        As[a_c0 + 0][a_r0] = av0.x; As[a_c0 + 1][a_r0] = av0.y;
        As[a_c0 + 2][a_r0] = av0.z; As[a_c0 + 3][a_r0] = av0.w;
        As[a_c0 + 0][64 + a_r0] = av1.x; As[a_c0 + 1][64 + a_r0] = av1.y;
        As[a_c0 + 2][64 + a_r0] = av1.z; As[a_c0 + 3][64 + a_r0] = av1.w;
        *(float4*)&Bs[b_r0][b_c0] = bv0;
        *(float4*)&Bs[8 + b_r0][b_c0] = bv1;
        __syncthreads();
#pragma unroll
        for (int kk = 0; kk < 16; kk++) {
            float a[8], bvv[8];
#pragma unroll
            for (int i = 0; i < 8; i++) a[i] = As[kk][tm + i];
#pragma unroll
            for (int j = 0; j < 8; j++) bvv[j] = Bs[kk][tn + j];
#pragma unroll
            for (int i = 0; i < 8; i++)
#pragma unroll
                for (int j = 0; j < 8; j++) acc[i][j] += a[i] * bvv[j];
        }
    }

#pragma unroll
    for (int i = 0; i < 8; i++) {
        size_t row = (size_t)(bm * 128 + tm + i);
        size_t cbase = row * N + bn * 128 + tn;
#pragma unroll
        for (int j = 0; j < 8; j += 4) {
            float4 r = make_float4(acc[i][j], acc[i][j + 1], acc[i][j + 2], acc[i][j + 3]);
            if (EPI == 1) {
                float4 xr = *(const float4*)&Res[cbase + j];
                r.x += xr.x; r.y += xr.y; r.z += xr.z; r.w += xr.w;
            }
            if (EPI == 2) {
                float4 xr = *(const float4*)&C[cbase + j];
                r.x += xr.x; r.y += xr.y; r.z += xr.z; r.w += xr.w;
            }
            *(float4*)&C[cbase + j] = r;
        }
    }
}

// ---------------- silu(gate)*up, in place into m1 ----------------
__global__ __launch_bounds__(256) void silu_k(float* __restrict__ m1,
                                              const float* __restrict__ m2) {
    size_t i0 = (size_t)blockIdx.x * 1024 + threadIdx.x;
#pragma unroll
    for (int i = 0; i < 4; i++) {
        size_t idx = i0 + i * 256;
        float g = m1[idx];
        float s = g / (1.f + expf(-g));
        m1[idx] = s * m2[idx];
    }
}

// ---------------- launch ----------------
extern "C" void kernel_launch(void* const* d_in, const int* in_sizes, int n_in,
                              void* d_out, int out_size) {
    const float* x   = (const float*)d_in[0];
    const float* n1w = (const float*)d_in[1];
    const float* Wq  = (const float*)d_in[2];
    const float* Wk  = (const float*)d_in[3];
    const float* Wv  = (const float*)d_in[4];
    const float* bw  = (const float*)d_in[5];
    const float* bbp = (const float*)d_in[6];
    const float* Wo  = (const float*)d_in[7];
    const float* al  = (const float*)d_in[8];
    const float* n2w = (const float*)d_in[9];
    const float* wg  = (const float*)d_in[10];
    const float* wu  = (const float*)d_in[11];
    const float* wd  = (const float*)d_in[12];
    float* out = (float*)d_out;

    float *h, *q, *k, *v, *beta, *m1, *m2;
    cudaGetSymbolAddress((void**)&h,    g_h);
    cudaGetSymbolAddress((void**)&q,    g_q);
    cudaGetSymbolAddress((void**)&k,    g_k);
    cudaGetSymbolAddress((void**)&v,    g_v);
    cudaGetSymbolAddress((void**)&beta, g_beta);
    cudaGetSymbolAddress((void**)&m1,   g_m1);
    cudaGetSymbolAddress((void**)&m2,   g_m2);

    // h = rmsnorm(x) * norm1_w
    rmsnorm_k<<<BT, 256>>>(x, n1w, h);
    // q,k,v projections
    sgemm<0><<<dim3(Dm / 128, BT / 128), 256>>>(h, Wq, q, nullptr, BT, Dm, Dm);
    sgemm<0><<<dim3(Dm / 128, BT / 128), 256>>>(h, Wk, k, nullptr, BT, Dm, Dm);
    sgemm<0><<<dim3(Dm / 128, BT / 128), 256>>>(h, Wv, v, nullptr, BT, Dm, Dm);
    // beta
    beta_k<<<BT / 8, 256>>>(h, bw, bbp, beta);
    // normalize k rows
    knorm_k<<<BT, 256>>>(k);
    // EMA scan on v
    ema_k<<<dim3(Dm / 256, Bb), 256>>>(v, al);
    // delta-rule scan -> attn (reuse h)
    delta_k<<<dim3(Dm / 32, Bb), 512>>>(q, k, v, beta, h);
    // out = x + attn @ Wo
    sgemm<1><<<dim3(Dm / 128, BT / 128), 256>>>(h, Wo, out, x, BT, Dm, Dm);
    // h2 = rmsnorm(out) (reuse q)
    rmsnorm_k<<<BT, 256>>>(out, n2w, q);
    // gate, up
    sgemm<0><<<dim3(HIDm / 128, BT / 128), 256>>>(q, wg, m1, nullptr, BT, HIDm, Dm);
    sgemm<0><<<dim3(HIDm / 128, BT / 128), 256>>>(q, wu, m2, nullptr, BT, HIDm, Dm);
    // m1 = silu(m1)*m2
    silu_k<<<(BT * HIDm) / 1024, 256>>>(m1, m2);
    // out += m1 @ w_down
    sgemm<2><<<dim3(Dm / 128, BT / 128), 256>>>(m1, wd, out, nullptr, BT, Dm, HIDm);
}

// round 3
// speedup vs baseline: 1.4831x; 1.4831x over previous
#include <cuda_runtime.h>
#include <math.h>
#include <stdint.h>

#define BT   8192
#define Dm   1024
#define HIDm 2048
#define Tlen 2048
#define Bb   4

typedef unsigned long long ull;

// ---- static scratch ----
__device__ float g_h[BT * Dm];
__device__ float g_q[BT * Dm];
__device__ float g_k[BT * Dm];
__device__ float g_v[BT * Dm];
__device__ float g_beta[BT];
__device__ float g_m1[BT * HIDm];
__device__ float g_m2[BT * HIDm];

// ================= helpers =================
__device__ __forceinline__ float to_tf32(float x) {
    float r;
    asm("cvt.rna.tf32.f32 %0, %1;" : "=f"(r) : "f"(x));
    return r;
}
__device__ __forceinline__ void mma_tf32(float4& c, uint32_t a0, uint32_t a1,
                                         uint32_t a2, uint32_t a3,
                                         uint32_t b0, uint32_t b1) {
    asm volatile(
        "mma.sync.aligned.m16n8k8.row.col.f32.tf32.tf32.f32 "
        "{%0,%1,%2,%3}, {%4,%5,%6,%7}, {%8,%9}, {%0,%1,%2,%3};"
        : "+f"(c.x), "+f"(c.y), "+f"(c.z), "+f"(c.w)
        : "r"(a0), "r"(a1), "r"(a2), "r"(a3), "r"(b0), "r"(b1));
}
__device__ __forceinline__ ull pk2(float a, float b) {
    ull r;
    asm("mov.b64 %0, {%1,%2};" : "=l"(r) : "f"(a), "f"(b));
    return r;
}
__device__ __forceinline__ float2 unpk2(ull v) {
    float2 f;
    asm("mov.b64 {%0,%1}, %2;" : "=f"(f.x), "=f"(f.y) : "l"(v));
    return f;
}
#define FMA2(d, a, b, c) asm("fma.rn.f32x2 %0, %1, %2, %3;" : "=l"(d) : "l"(a), "l"(b), "l"(c))

__device__ __forceinline__ float block_sum_256(float v) {
    __shared__ float sh[8];
    int lane = threadIdx.x & 31, wid = threadIdx.x >> 5;
#pragma unroll
    for (int o = 16; o; o >>= 1) v += __shfl_xor_sync(0xffffffffu, v, o);
    if (lane == 0) sh[wid] = v;
    __syncthreads();
    if (wid == 0) {
        float t = (lane < 8) ? sh[lane] : 0.f;
#pragma unroll
        for (int o = 4; o; o >>= 1) t += __shfl_xor_sync(0xffffffffu, t, o);
        if (lane == 0) sh[0] = t;
    }
    __syncthreads();
    return sh[0];
}

// ================= small kernels =================
__global__ __launch_bounds__(256) void rmsnorm_k(const float* __restrict__ x,
                                                 const float* __restrict__ w,
                                                 float* __restrict__ out) {
    int row = blockIdx.x;
    const float* xr = x + (size_t)row * Dm;
    float* orow = out + (size_t)row * Dm;
    float v[4];
    float ss = 0.f;
#pragma unroll
    for (int i = 0; i < 4; i++) {
        v[i] = xr[i * 256 + threadIdx.x];
        ss += v[i] * v[i];
    }
    float tot = block_sum_256(ss);
    float scale = rsqrtf(tot * (1.0f / Dm) + 1e-6f);
#pragma unroll
    for (int i = 0; i < 4; i++) {
        int c = i * 256 + threadIdx.x;
        orow[c] = v[i] * scale * w[c];
    }
}

__global__ __launch_bounds__(256) void knorm_k(float* __restrict__ k) {
    int row = blockIdx.x;
    float* kr = k + (size_t)row * Dm;
    float v[4];
    float ss = 0.f;
#pragma unroll
    for (int i = 0; i < 4; i++) {
        v[i] = kr[i * 256 + threadIdx.x];
        ss += v[i] * v[i];
    }
    float tot = block_sum_256(ss);
    float scale = 1.f / fmaxf(sqrtf(tot), 1e-12f);
#pragma unroll
    for (int i = 0; i < 4; i++) kr[i * 256 + threadIdx.x] = v[i] * scale;
}

__global__ __launch_bounds__(256) void beta_k(const float* __restrict__ h,
                                              const float* __restrict__ bw,
                                              const float* __restrict__ bb,
                                              float* __restrict__ beta) {
    int row = blockIdx.x * 8 + (threadIdx.x >> 5);
    int lane = threadIdx.x & 31;
    const float* hr = h + (size_t)row * Dm;
    float s = 0.f;
#pragma unroll
    for (int m = 0; m < 32; m++) s += hr[m * 32 + lane] * bw[m * 32 + lane];
#pragma unroll
    for (int o = 16; o; o >>= 1) s += __shfl_xor_sync(0xffffffffu, s, o);
    if (lane == 0) beta[row] = 1.f / (1.f + expf(-(s + bb[0])));
}

__global__ __launch_bounds__(256) void ema_k(float* __restrict__ v,
                                             const float* __restrict__ alpha_logit) {
    int d = blockIdx.x * 256 + threadIdx.x;
    int b = blockIdx.y;
    float a = 1.f / (1.f + expf(-alpha_logit[d]));
    float om = 1.f - a;
    float prev = 0.f;
    size_t idx = (size_t)b * Tlen * Dm + d;
    for (int t = 0; t < Tlen; t++, idx += Dm) {
        float cur = a * v[idx] + om * prev;
        v[idx] = cur;
        prev = cur;
    }
}

__global__ __launch_bounds__(256) void silu_k(float* __restrict__ m1,
                                              const float* __restrict__ m2) {
    size_t i0 = (size_t)blockIdx.x * 1024 + threadIdx.x;
#pragma unroll
    for (int i = 0; i < 4; i++) {
        size_t idx = i0 + i * 256;
        float g = m1[idx];
        float s = g / (1.f + expf(-g));
        m1[idx] = s * m2[idx];
    }
}

// ================= delta-rule scan (packed f32x2) =================
// grid (D/32, B), 512 threads. Warp w owns rows rowbase+2w, rowbase+2w+1.
// Lane l owns column pairs {64j+2l, 64j+2l+1}, j=0..15, packed in f32x2.
__global__ __launch_bounds__(512, 1) void delta_k(const float* __restrict__ q,
                                                  const float* __restrict__ k,
                                                  const float* __restrict__ v,
                                                  const float* __restrict__ beta,
                                                  float* __restrict__ o) {
    __shared__ __align__(16) float ksm[2][Dm];
    __shared__ __align__(16) float qsm[2][Dm];
    __shared__ __align__(16) float vsm[2][32];
    __shared__ float bsm[2];

    int b = blockIdx.y;
    int rowbase = blockIdx.x * 32;
    int tid = threadIdx.x;
    int lane = tid & 31, w = tid >> 5;

    const float* qb = q + (size_t)b * Tlen * Dm;
    const float* kb = k + (size_t)b * Tlen * Dm;
    const float* vb = v + (size_t)b * Tlen * Dm;
    const float* betab = beta + (size_t)b * Tlen;
    float* ob = o + (size_t)b * Tlen * Dm;

    ull S0[16], S1[16];
#pragma unroll
    for (int j = 0; j < 16; j++) { S0[j] = 0ull; S1[j] = 0ull; }

    // prologue: stage t=0 into buffer 0
    ((float2*)ksm[0])[tid] = ((const float2*)kb)[tid];
    ((float2*)qsm[0])[tid] = ((const float2*)qb)[tid];
    if (tid < 16) ((float2*)vsm[0])[tid] = ((const float2*)(vb + rowbase))[tid];
    if (tid == 0) bsm[0] = betab[0];
    __syncthreads();

    for (int t = 0; t < Tlen; t++) {
        int p = t & 1;
        // prefetch t+1 into other buffer (overlaps with compute below)
        if (t + 1 < Tlen) {
            size_t nb = (size_t)(t + 1) * Dm;
            ((float2*)ksm[p ^ 1])[tid] = ((const float2*)(kb + nb))[tid];
            ((float2*)qsm[p ^ 1])[tid] = ((const float2*)(qb + nb))[tid];
            if (tid < 16)
                ((float2*)vsm[p ^ 1])[tid] = ((const float2*)(vb + nb + rowbase))[tid];
            if (tid == 0) bsm[p ^ 1] = betab[t + 1];
        }

        const float* kp = ksm[p];
        const float* qp = qsm[p];

        // d = S . k (packed)
        ull d0p = 0ull, d1p = 0ull;
#pragma unroll
        for (int j = 0; j < 16; j++) {
            ull kk = *reinterpret_cast<const ull*>(&kp[j * 64 + 2 * lane]);
            FMA2(d0p, S0[j], kk, d0p);
            FMA2(d1p, S1[j], kk, d1p);
        }
        float2 f0 = unpk2(d0p), f1 = unpk2(d1p);
        float d0 = f0.x + f0.y, d1 = f1.x + f1.y;
#pragma unroll
        for (int off = 16; off; off >>= 1) {
            d0 += __shfl_xor_sync(0xffffffffu, d0, off);
            d1 += __shfl_xor_sync(0xffffffffu, d1, off);
        }
        float bt = bsm[p];
        float e0 = bt * (vsm[p][2 * w] - d0);
        float e1 = bt * (vsm[p][2 * w + 1] - d1);
        ull e0p = pk2(e0, e0), e1p = pk2(e1, e1);

        // S += e k ; o = S . q  (packed)
        ull o0p = 0ull, o1p = 0ull;
#pragma unroll
        for (int j = 0; j < 16; j++) {
            ull kk = *reinterpret_cast<const ull*>(&kp[j * 64 + 2 * lane]);
            ull qq = *reinterpret_cast<const ull*>(&qp[j * 64 + 2 * lane]);
            FMA2(S0[j], e0p, kk, S0[j]);
            FMA2(o0p, S0[j], qq, o0p);
            FMA2(S1[j], e1p, kk, S1[j]);
            FMA2(o1p, S1[j], qq, o1p);
        }
        float2 g0 = unpk2(o0p), g1 = unpk2(o1p);
        float o0 = g0.x + g0.y, o1 = g1.x + g1.y;
#pragma unroll
        for (int off = 16; off; off >>= 1) {
            o0 += __shfl_xor_sync(0xffffffffu, o0, off);
            o1 += __shfl_xor_sync(0xffffffffu, o1, off);
        }
        if (lane == 0) {
            float2 ov = make_float2(o0, o1);
            *reinterpret_cast<float2*>(&ob[(size_t)t * Dm + rowbase + 2 * w]) = ov;
        }
        __syncthreads();
    }
}

// ================= tf32 tensor-core GEMM =================
// C[M,N] = A[M,K] @ B[K,N], row-major. BM=128, BN=128, BK=16, 256 thr, 8 warps.
// warp_m = wid&1 (64 rows), warp_n = wid>>1 (32 cols). Warp: 4x4 m16n8k8 tiles.
// As: permuted [m][pos], stride 20: value (m,c) at m*20 + 4*(c&3) + (c>>2)
//   -> A-fragment (4 k-cols of one row) = one aligned float4.
// Bs: [k][n], stride 132.
// EPI 0: C = acc ; 1: C = Res + acc ; 2: C += acc
#define AST 20
#define BSTR 132
template <int EPI>
__global__ __launch_bounds__(256, 1) void tgemm(const float* __restrict__ A,
                                                const float* __restrict__ B,
                                                float* __restrict__ C,
                                                const float* __restrict__ Res,
                                                int M, int N, int K) {
    __shared__ __align__(16) float As[2][128 * AST];
    __shared__ __align__(16) float Bs[2][16 * BSTR];

    const int tid = threadIdx.x;
    const int lane = tid & 31, wid = tid >> 5;
    const int warp_m = wid & 1, warp_n = wid >> 1;
    const int gid = lane >> 2, tig = lane & 3;
    const int bm = blockIdx.y, bn = blockIdx.x;

    float4 acc[4][4];
#pragma unroll
    for (int i = 0; i < 4; i++)
#pragma unroll
        for (int j = 0; j < 4; j++) acc[i][j] = make_float4(0.f, 0.f, 0.f, 0.f);

    // global load mapping
    const int a_row = tid >> 1;          // 0..127
    const int a_c0 = (tid & 1) * 8;      // 0 or 8
    const int b_row = tid >> 4;          // 0..15
    const int b_c0 = (tid & 15) * 4;     // 0..60
    const float* Ag = A + (size_t)(bm * 128 + a_row) * K + a_c0;
    const float* Bg = B + (size_t)b_row * N + (size_t)bn * 128 + b_c0;

    const int abase = a_row * AST + 2 * (tid & 1);
    const int bbase = b_row * BSTR + b_c0;

    // prologue: tile 0
    float4 av0 = *(const float4*)(Ag);
    float4 av1 = *(const float4*)(Ag + 4);
    float4 bv0 = *(const float4*)(Bg);
    float4 bv1 = *(const float4*)(Bg + 64);
    {
        As[0][abase + 0] = to_tf32(av0.x);
        As[0][abase + 4] = to_tf32(av0.y);
        As[0][abase + 8] = to_tf32(av0.z);
        As[0][abase + 12] = to_tf32(av0.w);
        As[0][abase + 1] = to_tf32(av1.x);
        As[0][abase + 5] = to_tf32(av1.y);
        As[0][abase + 9] = to_tf32(av1.z);
        As[0][abase + 13] = to_tf32(av1.w);
        float4 t0 = make_float4(to_tf32(bv0.x), to_tf32(bv0.y), to_tf32(bv0.z), to_tf32(bv0.w));
        float4 t1 = make_float4(to_tf32(bv1.x), to_tf32(bv1.y), to_tf32(bv1.z), to_tf32(bv1.w));
        *(float4*)&Bs[0][bbase] = t0;
        *(float4*)&Bs[0][bbase + 64] = t1;
    }
    __syncthreads();

    int p = 0;
    for (int kt = 16; kt <= K; kt += 16) {
        bool has = kt < K;
        if (has) {
            av0 = *(const float4*)(Ag + kt);
            av1 = *(const float4*)(Ag + kt + 4);
            const float* bgn = Bg + (size_t)kt * N;
            bv0 = *(const float4*)(bgn);
            bv1 = *(const float4*)(bgn + 64);
        }

        // A fragments (both k-steps packed in float4s)
        float4 fa[4], fb[4];
#pragma unroll
        for (int mt = 0; mt < 4; mt++) {
            int r0 = warp_m * 64 + mt * 16 + gid;
            fa[mt] = *(const float4*)&As[p][r0 * AST + tig * 4];
            fb[mt] = *(const float4*)&As[p][(r0 + 8) * AST + tig * 4];
        }
#pragma unroll
        for (int s = 0; s < 2; s++) {
            float b0v[4], b1v[4];
#pragma unroll
            for (int nt = 0; nt < 4; nt++) {
                int cn = warp_n * 32 + nt * 8 + gid;
                b0v[nt] = Bs[p][(8 * s + tig) * BSTR + cn];
                b1v[nt] = Bs[p][(8 * s + tig + 4) * BSTR + cn];
            }
#pragma unroll
            for (int mt = 0; mt < 4; mt++) {
                uint32_t A0 = __float_as_uint(s ? fa[mt].z : fa[mt].x);
                uint32_t A2 = __float_as_uint(s ? fa[mt].w : fa[mt].y);
                uint32_t A1 = __float_as_uint(s ? fb[mt].z : fb[mt].x);
                uint32_t A3 = __float_as_uint(s ? fb[mt].w : fb[mt].y);
#pragma unroll
                for (int nt = 0; nt < 4; nt++) {
                    mma_tf32(acc[mt][nt], A0, A1, A2, A3,
                             __float_as_uint(b0v[nt]), __float_as_uint(b1v[nt]));
                }
            }
        }

        if (has) {
            int np = p ^ 1;
            As[np][abase + 0] = to_tf32(av0.x);
            As[np][abase + 4] = to_tf32(av0.y);
            As[np][abase + 8] = to_tf32(av0.z);
            As[np][abase + 12] = to_tf32(av0.w);
            As[np][abase + 1] = to_tf32(av1.x);
            As[np][abase + 5] = to_tf32(av1.y);
            As[np][abase + 9] = to_tf32(av1.z);
            As[np][abase + 13] = to_tf32(av1.w);
            float4 t0 = make_float4(to_tf32(bv0.x), to_tf32(bv0.y), to_tf32(bv0.z), to_tf32(bv0.w));
            float4 t1 = make_float4(to_tf32(bv1.x), to_tf32(bv1.y), to_tf32(bv1.z), to_tf32(bv1.w));
            *(float4*)&Bs[np][bbase] = t0;
            *(float4*)&Bs[np][bbase + 64] = t1;
        }
        __syncthreads();
        p ^= 1;
    }

    // epilogue
#pragma unroll
    for (int mt = 0; mt < 4; mt++) {
        size_t r0 = (size_t)(bm * 128 + warp_m * 64 + mt * 16 + gid);
#pragma unroll
        for (int nt = 0; nt < 4; nt++) {
            size_t cg = (size_t)(bn * 128 + warp_n * 32 + nt * 8 + 2 * tig);
            size_t i0 = r0 * N + cg;
            size_t i1 = (r0 + 8) * N + cg;
            float2 v0 = make_float2(acc[mt][nt].x, acc[mt][nt].y);
            float2 v1 = make_float2(acc[mt][nt].z, acc[mt][nt].w);
            if (EPI == 1) {
                float2 x0 = *(const float2*)&Res[i0];
                float2 x1 = *(const float2*)&Res[i1];
                v0.x += x0.x; v0.y += x0.y; v1.x += x1.x; v1.y += x1.y;
            }
            if (EPI == 2) {
                float2 x0 = *(const float2*)&C[i0];
                float2 x1 = *(const float2*)&C[i1];
                v0.x += x0.x; v0.y += x0.y; v1.x += x1.x; v1.y += x1.y;
            }
            *(float2*)&C[i0] = v0;
            *(float2*)&C[i1] = v1;
        }
    }
}

// ================= launch =================
extern "C" void kernel_launch(void* const* d_in, const int* in_sizes, int n_in,
                              void* d_out, int out_size) {
    const float* x   = (const float*)d_in[0];
    const float* n1w = (const float*)d_in[1];
    const float* Wq  = (const float*)d_in[2];
    const float* Wk  = (const float*)d_in[3];
    const float* Wv  = (const float*)d_in[4];
    const float* bw  = (const float*)d_in[5];
    const float* bbp = (const float*)d_in[6];
    const float* Wo  = (const float*)d_in[7];
    const float* al  = (const float*)d_in[8];
    const float* n2w = (const float*)d_in[9];
    const float* wg  = (const float*)d_in[10];
    const float* wu  = (const float*)d_in[11];
    const float* wd  = (const float*)d_in[12];
    float* out = (float*)d_out;

    float *h, *q, *k, *v, *beta, *m1, *m2;
    cudaGetSymbolAddress((void**)&h,    g_h);
    cudaGetSymbolAddress((void**)&q,    g_q);
    cudaGetSymbolAddress((void**)&k,    g_k);
    cudaGetSymbolAddress((void**)&v,    g_v);
    cudaGetSymbolAddress((void**)&beta, g_beta);
    cudaGetSymbolAddress((void**)&m1,   g_m1);
    cudaGetSymbolAddress((void**)&m2,   g_m2);

    rmsnorm_k<<<BT, 256>>>(x, n1w, h);

    tgemm<0><<<dim3(Dm / 128, BT / 128), 256>>>(h, Wq, q, nullptr, BT, Dm, Dm);
    tgemm<0><<<dim3(Dm / 128, BT / 128), 256>>>(h, Wk, k, nullptr, BT, Dm, Dm);
    tgemm<0><<<dim3(Dm / 128, BT / 128), 256>>>(h, Wv, v, nullptr, BT, Dm, Dm);

    beta_k<<<BT / 8, 256>>>(h, bw, bbp, beta);
    knorm_k<<<BT, 256>>>(k);
    ema_k<<<dim3(Dm / 256, Bb), 256>>>(v, al);

    delta_k<<<dim3(Dm / 32, Bb), 512>>>(q, k, v, beta, h);

    tgemm<1><<<dim3(Dm / 128, BT / 128), 256>>>(h, Wo, out, x, BT, Dm, Dm);
    rmsnorm_k<<<BT, 256>>>(out, n2w, q);

    tgemm<0><<<dim3(HIDm / 128, BT / 128), 256>>>(q, wg, m1, nullptr, BT, HIDm, Dm);
    tgemm<0><<<dim3(HIDm / 128, BT / 128), 256>>>(q, wu, m2, nullptr, BT, HIDm, Dm);
    silu_k<<<(BT * HIDm) / 1024, 256>>>(m1, m2);
    tgemm<2><<<dim3(Dm / 128, BT / 128), 256>>>(m1, wd, out, nullptr, BT, Dm, HIDm);
}

// round 6
// speedup vs baseline: 1.6816x; 1.1339x over previous
#include <cuda_runtime.h>
#include <math.h>
#include <stdint.h>

#define BT   8192
#define Dm   1024
#define HIDm 2048
#define Tlen 2048
#define Bb   4

typedef unsigned long long ull;

// ---- static scratch ----
__device__ float g_h[BT * Dm];
__device__ float g_q[BT * Dm];
__device__ float g_k[BT * Dm];
__device__ float g_v[BT * Dm];
__device__ float g_beta[BT];
__device__ float g_m1[BT * HIDm];
__device__ float g_m2[BT * HIDm];
// tf32-rounded weights: Wq,Wk,Wv,Wo (1M each), wg,wu,wd (2M each)
__device__ float g_wt[10 * 1024 * 1024];

// ================= helpers =================
__device__ __forceinline__ float to_tf32(float x) {
    float r;
    asm("cvt.rna.tf32.f32 %0, %1;" : "=f"(r) : "f"(x));
    return r;
}
__device__ __forceinline__ void mma_tf32(float4& c, uint32_t a0, uint32_t a1,
                                         uint32_t a2, uint32_t a3,
                                         uint32_t b0, uint32_t b1) {
    asm volatile(
        "mma.sync.aligned.m16n8k8.row.col.f32.tf32.tf32.f32 "
        "{%0,%1,%2,%3}, {%4,%5,%6,%7}, {%8,%9}, {%0,%1,%2,%3};"
        : "+f"(c.x), "+f"(c.y), "+f"(c.z), "+f"(c.w)
        : "r"(a0), "r"(a1), "r"(a2), "r"(a3), "r"(b0), "r"(b1));
}
__device__ __forceinline__ void cpa16(void* smem, const void* gmem) {
    uint32_t sa = (uint32_t)__cvta_generic_to_shared(smem);
    asm volatile("cp.async.ca.shared.global [%0], [%1], 16;" :: "r"(sa), "l"(gmem));
}
#define CP_COMMIT() asm volatile("cp.async.commit_group;")
#define CP_WAIT(n)  asm volatile("cp.async.wait_group %0;" :: "n"(n))

__device__ __forceinline__ ull pk2(float a, float b) {
    ull r;
    asm("mov.b64 %0, {%1,%2};" : "=l"(r) : "f"(a), "f"(b));
    return r;
}
__device__ __forceinline__ float2 unpk2(ull v) {
    float2 f;
    asm("mov.b64 {%0,%1}, %2;" : "=f"(f.x), "=f"(f.y) : "l"(v));
    return f;
}
#define FMA2(d, a, b, c) asm("fma.rn.f32x2 %0, %1, %2, %3;" : "=l"(d) : "l"(a), "l"(b), "l"(c))

__device__ __forceinline__ float block_sum_256(float v) {
    __shared__ float sh[8];
    int lane = threadIdx.x & 31, wid = threadIdx.x >> 5;
#pragma unroll
    for (int o = 16; o; o >>= 1) v += __shfl_xor_sync(0xffffffffu, v, o);
    if (lane == 0) sh[wid] = v;
    __syncthreads();
    if (wid == 0) {
        float t = (lane < 8) ? sh[lane] : 0.f;
#pragma unroll
        for (int o = 4; o; o >>= 1) t += __shfl_xor_sync(0xffffffffu, t, o);
        if (lane == 0) sh[0] = t;
    }
    __syncthreads();
    return sh[0];
}

// ================= small kernels =================
// CVT: round output to tf32 (it feeds a GEMM)
template <bool CVT>
__global__ __launch_bounds__(256) void rmsnorm_k(const float* __restrict__ x,
                                                 const float* __restrict__ w,
                                                 float* __restrict__ out) {
    int row = blockIdx.x;
    const float* xr = x + (size_t)row * Dm;
    float* orow = out + (size_t)row * Dm;
    float v[4];
    float ss = 0.f;
#pragma unroll
    for (int i = 0; i < 4; i++) {
        v[i] = xr[i * 256 + threadIdx.x];
        ss += v[i] * v[i];
    }
    float tot = block_sum_256(ss);
    float scale = rsqrtf(tot * (1.0f / Dm) + 1e-6f);
#pragma unroll
    for (int i = 0; i < 4; i++) {
        int c = i * 256 + threadIdx.x;
        float r = v[i] * scale * w[c];
        orow[c] = CVT ? to_tf32(r) : r;
    }
}

__global__ __launch_bounds__(256) void knorm_k(float* __restrict__ k) {
    int row = blockIdx.x;
    float* kr = k + (size_t)row * Dm;
    float v[4];
    float ss = 0.f;
#pragma unroll
    for (int i = 0; i < 4; i++) {
        v[i] = kr[i * 256 + threadIdx.x];
        ss += v[i] * v[i];
    }
    float tot = block_sum_256(ss);
    float scale = 1.f / fmaxf(sqrtf(tot), 1e-12f);
#pragma unroll
    for (int i = 0; i < 4; i++) kr[i * 256 + threadIdx.x] = v[i] * scale;
}

__global__ __launch_bounds__(256) void beta_k(const float* __restrict__ h,
                                              const float* __restrict__ bw,
                                              const float* __restrict__ bb,
                                              float* __restrict__ beta) {
    int row = blockIdx.x * 8 + (threadIdx.x >> 5);
    int lane = threadIdx.x & 31;
    const float* hr = h + (size_t)row * Dm;
    float s = 0.f;
#pragma unroll
    for (int m = 0; m < 32; m++) s += hr[m * 32 + lane] * bw[m * 32 + lane];
#pragma unroll
    for (int o = 16; o; o >>= 1) s += __shfl_xor_sync(0xffffffffu, s, o);
    if (lane == 0) beta[row] = 1.f / (1.f + expf(-(s + bb[0])));
}

// EMA with MLP=16 prefetch batches
__global__ __launch_bounds__(256) void ema_k(float* __restrict__ v,
                                             const float* __restrict__ alpha_logit) {
    int d = blockIdx.x * 256 + threadIdx.x;
    int b = blockIdx.y;
    float a = 1.f / (1.f + expf(-alpha_logit[d]));
    float om = 1.f - a;
    float prev = 0.f;
    size_t idx = (size_t)b * Tlen * Dm + d;
    for (int t0 = 0; t0 < Tlen; t0 += 16) {
        float xv[16];
#pragma unroll
        for (int i = 0; i < 16; i++) xv[i] = v[idx + (size_t)i * Dm];
#pragma unroll
        for (int i = 0; i < 16; i++) {
            prev = fmaf(a, xv[i], om * prev);
            xv[i] = prev;
        }
#pragma unroll
        for (int i = 0; i < 16; i++) v[idx + (size_t)i * Dm] = xv[i];
        idx += (size_t)16 * Dm;
    }
}

__global__ __launch_bounds__(256) void silu_k(float* __restrict__ m1,
                                              const float* __restrict__ m2) {
    size_t i0 = (size_t)blockIdx.x * 1024 + threadIdx.x;
#pragma unroll
    for (int i = 0; i < 4; i++) {
        size_t idx = i0 + i * 256;
        float g = m1[idx];
        float s = g / (1.f + expf(-g));
        m1[idx] = to_tf32(s * m2[idx]);
    }
}

// copy-convert weights to tf32 (float4 per thread)
__global__ __launch_bounds__(256) void cvt_k(const float* __restrict__ in,
                                             float* __restrict__ out) {
    size_t i = (size_t)blockIdx.x * 256 + threadIdx.x;
    float4 v = ((const float4*)in)[i];
    v.x = to_tf32(v.x); v.y = to_tf32(v.y);
    v.z = to_tf32(v.z); v.w = to_tf32(v.w);
    ((float4*)out)[i] = v;
}

// ================= delta-rule scan (packed f32x2) =================
__global__ __launch_bounds__(512, 1) void delta_k(const float* __restrict__ q,
                                                  const float* __restrict__ k,
                                                  const float* __restrict__ v,
                                                  const float* __restrict__ beta,
                                                  float* __restrict__ o) {
    __shared__ __align__(16) float ksm[2][Dm];
    __shared__ __align__(16) float qsm[2][Dm];
    __shared__ __align__(16) float vsm[2][32];
    __shared__ float bsm[2];

    int b = blockIdx.y;
    int rowbase = blockIdx.x * 32;
    int tid = threadIdx.x;
    int lane = tid & 31, w = tid >> 5;

    const float* qb = q + (size_t)b * Tlen * Dm;
    const float* kb = k + (size_t)b * Tlen * Dm;
    const float* vb = v + (size_t)b * Tlen * Dm;
    const float* betab = beta + (size_t)b * Tlen;
    float* ob = o + (size_t)b * Tlen * Dm;

    ull S0[16], S1[16];
#pragma unroll
    for (int j = 0; j < 16; j++) { S0[j] = 0ull; S1[j] = 0ull; }

    ((float2*)ksm[0])[tid] = ((const float2*)kb)[tid];
    ((float2*)qsm[0])[tid] = ((const float2*)qb)[tid];
    if (tid < 16) ((float2*)vsm[0])[tid] = ((const float2*)(vb + rowbase))[tid];
    if (tid == 0) bsm[0] = betab[0];
    __syncthreads();

    for (int t = 0; t < Tlen; t++) {
        int p = t & 1;
        if (t + 1 < Tlen) {
            size_t nb = (size_t)(t + 1) * Dm;
            ((float2*)ksm[p ^ 1])[tid] = ((const float2*)(kb + nb))[tid];
            ((float2*)qsm[p ^ 1])[tid] = ((const float2*)(qb + nb))[tid];
            if (tid < 16)
                ((float2*)vsm[p ^ 1])[tid] = ((const float2*)(vb + nb + rowbase))[tid];
            if (tid == 0) bsm[p ^ 1] = betab[t + 1];
        }

        const float* kp = ksm[p];
        const float* qp = qsm[p];

        ull d0p = 0ull, d1p = 0ull;
#pragma unroll
        for (int j = 0; j < 16; j++) {
            ull kk = *reinterpret_cast<const ull*>(&kp[j * 64 + 2 * lane]);
            FMA2(d0p, S0[j], kk, d0p);
            FMA2(d1p, S1[j], kk, d1p);
        }
        float2 f0 = unpk2(d0p), f1 = unpk2(d1p);
        float d0 = f0.x + f0.y, d1 = f1.x + f1.y;
#pragma unroll
        for (int off = 16; off; off >>= 1) {
            d0 += __shfl_xor_sync(0xffffffffu, d0, off);
            d1 += __shfl_xor_sync(0xffffffffu, d1, off);
        }
        float bt = bsm[p];
        float e0 = bt * (vsm[p][2 * w] - d0);
        float e1 = bt * (vsm[p][2 * w + 1] - d1);
        ull e0p = pk2(e0, e0), e1p = pk2(e1, e1);

        ull o0p = 0ull, o1p = 0ull;
#pragma unroll
        for (int j = 0; j < 16; j++) {
            ull kk = *reinterpret_cast<const ull*>(&kp[j * 64 + 2 * lane]);
            ull qq = *reinterpret_cast<const ull*>(&qp[j * 64 + 2 * lane]);
            FMA2(S0[j], e0p, kk, S0[j]);
            FMA2(o0p, S0[j], qq, o0p);
            FMA2(S1[j], e1p, kk, S1[j]);
            FMA2(o1p, S1[j], qq, o1p);
        }
        float2 g0 = unpk2(o0p), g1 = unpk2(o1p);
        float o0 = g0.x + g0.y, o1 = g1.x + g1.y;
#pragma unroll
        for (int off = 16; off; off >>= 1) {
            o0 += __shfl_xor_sync(0xffffffffu, o0, off);
            o1 += __shfl_xor_sync(0xffffffffu, o1, off);
        }
        if (lane == 0) {
            float2 ov = make_float2(to_tf32(o0), to_tf32(o1));
            *reinterpret_cast<float2*>(&ob[(size_t)t * Dm + rowbase + 2 * w]) = ov;
        }
        __syncthreads();
    }
}

// ================= tf32 tensor-core GEMM, cp.async 3-stage =================
// Inputs MUST already be tf32-rounded. BM=BN=128, BK=16, 256 thr, 8 warps,
// warp tile 64x32 (warp_m=wid&1, warp_n=wid>>1), 4x4 m16n8k8 per warp.
#define AST 20    // A smem row stride (floats), bank-conflict-free
#define BSTR 136  // B smem row stride (floats), bank-conflict-free
#define STAGES 3

template <int EPI>
__global__ __launch_bounds__(256, 2) void tgemm(const float* __restrict__ A,
                                                const float* __restrict__ B,
                                                float* __restrict__ C,
                                                const float* __restrict__ Res,
                                                int M, int N, int K) {
    __shared__ __align__(16) float As[STAGES][128 * AST];
    __shared__ __align__(16) float Bs[STAGES][16 * BSTR];

    const int tid = threadIdx.x;
    const int lane = tid & 31, wid = tid >> 5;
    const int warp_m = wid & 1, warp_n = wid >> 1;
    const int gid = lane >> 2, tig = lane & 3;
    const int bm = blockIdx.y, bn = blockIdx.x;

    float4 acc[4][4];
#pragma unroll
    for (int i = 0; i < 4; i++)
#pragma unroll
        for (int j = 0; j < 4; j++) acc[i][j] = make_float4(0.f, 0.f, 0.f, 0.f);

    const float* Ag = A + (size_t)(bm * 128) * K;
    const float* Bg = B + (size_t)bn * 128;

    // copy mapping: 2 A-chunks + 2 B-chunks (16B) per thread per stage
    const int ca0 = tid * 2;
    const int a_r0 = ca0 >> 2, a_cc0 = (ca0 & 3) * 4;
    const int a_r1 = (ca0 + 1) >> 2, a_cc1 = ((ca0 + 1) & 3) * 4;
    const int b_r0 = ca0 >> 5, b_cc0 = (ca0 & 31) * 4;
    const int b_r1 = (ca0 + 1) >> 5, b_cc1 = ((ca0 + 1) & 31) * 4;

    const int ktiles = K >> 4;

    auto issue = [&](int st, int kt) {
        float* as = As[st];
        float* bs = Bs[st];
        const float* ag = Ag + kt * 16;
        const float* bg = Bg + (size_t)(kt * 16) * N;
        cpa16(as + a_r0 * AST + a_cc0, ag + (size_t)a_r0 * K + a_cc0);
        cpa16(as + a_r1 * AST + a_cc1, ag + (size_t)a_r1 * K + a_cc1);
        cpa16(bs + b_r0 * BSTR + b_cc0, bg + (size_t)b_r0 * N + b_cc0);
        cpa16(bs + b_r1 * BSTR + b_cc1, bg + (size_t)b_r1 * N + b_cc1);
    };

    // prologue: stages 0..STAGES-2
#pragma unroll
    for (int s = 0; s < STAGES - 1; s++) {
        issue(s, s);
        CP_COMMIT();
    }

    int st = 0;
    for (int kt = 0; kt < ktiles; kt++) {
        CP_WAIT(STAGES - 2);
        __syncthreads();
        int nk = kt + STAGES - 1;
        if (nk < ktiles) issue((st + STAGES - 1) % STAGES, nk);
        CP_COMMIT();

        const float* as = As[st];
        const float* bs = Bs[st];
#pragma unroll
        for (int s = 0; s < 2; s++) {
            float a0[4], a1[4], a2[4], a3[4];
#pragma unroll
            for (int mt = 0; mt < 4; mt++) {
                const float* ap = as + (warp_m * 64 + mt * 16 + gid) * AST + 8 * s + tig;
                a0[mt] = ap[0];
                a2[mt] = ap[4];
                a1[mt] = ap[8 * AST];
                a3[mt] = ap[8 * AST + 4];
            }
#pragma unroll
            for (int nt = 0; nt < 4; nt++) {
                int cn = warp_n * 32 + nt * 8 + gid;
                float b0 = bs[(8 * s + tig) * BSTR + cn];
                float b1 = bs[(8 * s + tig + 4) * BSTR + cn];
#pragma unroll
                for (int mt = 0; mt < 4; mt++) {
                    mma_tf32(acc[mt][nt],
                             __float_as_uint(a0[mt]), __float_as_uint(a1[mt]),
                             __float_as_uint(a2[mt]), __float_as_uint(a3[mt]),
                             __float_as_uint(b0), __float_as_uint(b1));
                }
            }
        }
        st = (st + 1) % STAGES;
    }

    // epilogue
#pragma unroll
    for (int mt = 0; mt < 4; mt++) {
        size_t r0 = (size_t)(bm * 128 + warp_m * 64 + mt * 16 + gid);
#pragma unroll
        for (int nt = 0; nt < 4; nt++) {
            size_t cg = (size_t)(bn * 128 + warp_n * 32 + nt * 8 + 2 * tig);
            size_t i0 = r0 * N + cg;
            size_t i1 = (r0 + 8) * N + cg;
            float2 v0 = make_float2(acc[mt][nt].x, acc[mt][nt].y);
            float2 v1 = make_float2(acc[mt][nt].z, acc[mt][nt].w);
            if (EPI == 1) {
                float2 x0 = *(const float2*)&Res[i0];
                float2 x1 = *(const float2*)&Res[i1];
                v0.x += x0.x; v0.y += x0.y; v1.x += x1.x; v1.y += x1.y;
            }
            if (EPI == 2) {
                float2 x0 = *(const float2*)&C[i0];
                float2 x1 = *(const float2*)&C[i1];
                v0.x += x0.x; v0.y += x0.y; v1.x += x1.x; v1.y += x1.y;
            }
            *(float2*)&C[i0] = v0;
            *(float2*)&C[i1] = v1;
        }
    }
}

// ================= launch =================
extern "C" void kernel_launch(void* const* d_in, const int* in_sizes, int n_in,
                              void* d_out, int out_size) {
    const float* x   = (const float*)d_in[0];
    const float* n1w = (const float*)d_in[1];
    const float* Wq  = (const float*)d_in[2];
    const float* Wk  = (const float*)d_in[3];
    const float* Wv  = (const float*)d_in[4];
    const float* bw  = (const float*)d_in[5];
    const float* bbp = (const float*)d_in[6];
    const float* Wo  = (const float*)d_in[7];
    const float* al  = (const float*)d_in[8];
    const float* n2w = (const float*)d_in[9];
    const float* wg  = (const float*)d_in[10];
    const float* wu  = (const float*)d_in[11];
    const float* wd  = (const float*)d_in[12];
    float* out = (float*)d_out;

    float *h, *q, *k, *v, *beta, *m1, *m2, *wt;
    cudaGetSymbolAddress((void**)&h,    g_h);
    cudaGetSymbolAddress((void**)&q,    g_q);
    cudaGetSymbolAddress((void**)&k,    g_k);
    cudaGetSymbolAddress((void**)&v,    g_v);
    cudaGetSymbolAddress((void**)&beta, g_beta);
    cudaGetSymbolAddress((void**)&m1,   g_m1);
    cudaGetSymbolAddress((void**)&m2,   g_m2);
    cudaGetSymbolAddress((void**)&wt,   g_wt);

    float* cWq = wt;                       // 1M
    float* cWk = wt + 1024 * 1024;         // 1M
    float* cWv = wt + 2 * 1024 * 1024;     // 1M
    float* cWo = wt + 3 * 1024 * 1024;     // 1M
    float* cWg = wt + 4 * 1024 * 1024;     // 2M
    float* cWu = wt + 6 * 1024 * 1024;     // 2M
    float* cWd = wt + 8 * 1024 * 1024;     // 2M

    // weight conversions (tf32 round into scratch)
    cvt_k<<<1024, 256>>>(Wq, cWq);
    cvt_k<<<1024, 256>>>(Wk, cWk);
    cvt_k<<<1024, 256>>>(Wv, cWv);
    cvt_k<<<1024, 256>>>(Wo, cWo);
    cvt_k<<<2048, 256>>>(wg, cWg);
    cvt_k<<<2048, 256>>>(wu, cWu);
    cvt_k<<<2048, 256>>>(wd, cWd);

    // h = tf32(rmsnorm(x) * norm1_w)
    rmsnorm_k<true><<<BT, 256>>>(x, n1w, h);

    tgemm<0><<<dim3(Dm / 128, BT / 128), 256>>>(h, cWq, q, nullptr, BT, Dm, Dm);
    tgemm<0><<<dim3(Dm / 128, BT / 128), 256>>>(h, cWk, k, nullptr, BT, Dm, Dm);
    tgemm<0><<<dim3(Dm / 128, BT / 128), 256>>>(h, cWv, v, nullptr, BT, Dm, Dm);

    beta_k<<<BT / 8, 256>>>(h, bw, bbp, beta);
    knorm_k<<<BT, 256>>>(k);
    ema_k<<<dim3(Dm / 256, Bb), 256>>>(v, al);

    delta_k<<<dim3(Dm / 32, Bb), 512>>>(q, k, v, beta, h);

    tgemm<1><<<dim3(Dm / 128, BT / 128), 256>>>(h, cWo, out, x, BT, Dm, Dm);
    rmsnorm_k<true><<<BT, 256>>>(out, n2w, q);

    tgemm<0><<<dim3(HIDm / 128, BT / 128), 256>>>(q, cWg, m1, nullptr, BT, HIDm, Dm);
    tgemm<0><<<dim3(HIDm / 128, BT / 128), 256>>>(q, cWu, m2, nullptr, BT, HIDm, Dm);
    silu_k<<<(BT * HIDm) / 1024, 256>>>(m1, m2);
    tgemm<2><<<dim3(Dm / 128, BT / 128), 256>>>(m1, cWd, out, nullptr, BT, Dm, HIDm);
}

// round 9
// speedup vs baseline: 1.7957x; 1.0679x over previous
#include <cuda_runtime.h>
#include <math.h>
#include <stdint.h>

#define BT   8192
#define Dm   1024
#define HIDm 2048
#define Tlen 2048
#define Bb   4

typedef unsigned long long ull;

// ---- static scratch ----
__device__ float g_h[BT * Dm];
__device__ float g_q[BT * Dm];
__device__ float g_k[BT * Dm];
__device__ float g_v[BT * Dm];
__device__ float g_beta[BT];
__device__ float g_m1[BT * HIDm];
__device__ float g_m2[BT * HIDm];
// tf32-rounded weights: Wq,Wk,Wv,Wo (1M each), wg,wu,wd (2M each)
__device__ float g_wt[10 * 1024 * 1024];

// ================= helpers =================
__device__ __forceinline__ float to_tf32(float x) {
    float r;
    asm("cvt.rna.tf32.f32 %0, %1;" : "=f"(r) : "f"(x));
    return r;
}
__device__ __forceinline__ void mma_tf32(float4& c, uint32_t a0, uint32_t a1,
                                         uint32_t a2, uint32_t a3,
                                         uint32_t b0, uint32_t b1) {
    asm volatile(
        "mma.sync.aligned.m16n8k8.row.col.f32.tf32.tf32.f32 "
        "{%0,%1,%2,%3}, {%4,%5,%6,%7}, {%8,%9}, {%0,%1,%2,%3};"
        : "+f"(c.x), "+f"(c.y), "+f"(c.z), "+f"(c.w)
        : "r"(a0), "r"(a1), "r"(a2), "r"(a3), "r"(b0), "r"(b1));
}
__device__ __forceinline__ void cpa16(void* smem, const void* gmem) {
    uint32_t sa = (uint32_t)__cvta_generic_to_shared(smem);
    asm volatile("cp.async.ca.shared.global [%0], [%1], 16;" :: "r"(sa), "l"(gmem));
}
#define CP_COMMIT() asm volatile("cp.async.commit_group;")
#define CP_WAIT(n)  asm volatile("cp.async.wait_group %0;" :: "n"(n))

__device__ __forceinline__ ull pk2(float a, float b) {
    ull r;
    asm("mov.b64 %0, {%1,%2};" : "=l"(r) : "f"(a), "f"(b));
    return r;
}
__device__ __forceinline__ float2 unpk2(ull v) {
    float2 f;
    asm("mov.b64 {%0,%1}, %2;" : "=f"(f.x), "=f"(f.y) : "l"(v));
    return f;
}
__device__ __forceinline__ float hsum2(ull v) {
    float2 f = unpk2(v);
    return f.x + f.y;
}
#define FMA2(d, a, b, c) asm("fma.rn.f32x2 %0, %1, %2, %3;" : "=l"(d) : "l"(a), "l"(b), "l"(c))

__device__ __forceinline__ float block_sum_256(float v) {
    __shared__ float sh[8];
    int lane = threadIdx.x & 31, wid = threadIdx.x >> 5;
#pragma unroll
    for (int o = 16; o; o >>= 1) v += __shfl_xor_sync(0xffffffffu, v, o);
    if (lane == 0) sh[wid] = v;
    __syncthreads();
    if (wid == 0) {
        float t = (lane < 8) ? sh[lane] : 0.f;
#pragma unroll
        for (int o = 4; o; o >>= 1) t += __shfl_xor_sync(0xffffffffu, t, o);
        if (lane == 0) sh[0] = t;
    }
    __syncthreads();
    return sh[0];
}

// ================= small kernels =================
template <bool CVT>
__global__ __launch_bounds__(256) void rmsnorm_k(const float* __restrict__ x,
                                                 const float* __restrict__ w,
                                                 float* __restrict__ out) {
    int row = blockIdx.x;
    const float* xr = x + (size_t)row * Dm;
    float* orow = out + (size_t)row * Dm;
    float v[4];
    float ss = 0.f;
#pragma unroll
    for (int i = 0; i < 4; i++) {
        v[i] = xr[i * 256 + threadIdx.x];
        ss += v[i] * v[i];
    }
    float tot = block_sum_256(ss);
    float scale = rsqrtf(tot * (1.0f / Dm) + 1e-6f);
#pragma unroll
    for (int i = 0; i < 4; i++) {
        int c = i * 256 + threadIdx.x;
        float r = v[i] * scale * w[c];
        orow[c] = CVT ? to_tf32(r) : r;
    }
}

__global__ __launch_bounds__(256) void knorm_k(float* __restrict__ k) {
    int row = blockIdx.x;
    float* kr = k + (size_t)row * Dm;
    float v[4];
    float ss = 0.f;
#pragma unroll
    for (int i = 0; i < 4; i++) {
        v[i] = kr[i * 256 + threadIdx.x];
        ss += v[i] * v[i];
    }
    float tot = block_sum_256(ss);
    float scale = 1.f / fmaxf(sqrtf(tot), 1e-12f);
#pragma unroll
    for (int i = 0; i < 4; i++) kr[i * 256 + threadIdx.x] = v[i] * scale;
}

__global__ __launch_bounds__(256) void beta_k(const float* __restrict__ h,
                                              const float* __restrict__ bw,
                                              const float* __restrict__ bb,
                                              float* __restrict__ beta) {
    int row = blockIdx.x * 8 + (threadIdx.x >> 5);
    int lane = threadIdx.x & 31;
    const float* hr = h + (size_t)row * Dm;
    float s = 0.f;
#pragma unroll
    for (int m = 0; m < 32; m++) s += hr[m * 32 + lane] * bw[m * 32 + lane];
#pragma unroll
    for (int o = 16; o; o >>= 1) s += __shfl_xor_sync(0xffffffffu, s, o);
    if (lane == 0) beta[row] = 1.f / (1.f + expf(-(s + bb[0])));
}

__global__ __launch_bounds__(256) void ema_k(float* __restrict__ v,
                                             const float* __restrict__ alpha_logit) {
    int d = blockIdx.x * 256 + threadIdx.x;
    int b = blockIdx.y;
    float a = 1.f / (1.f + expf(-alpha_logit[d]));
    float om = 1.f - a;
    float prev = 0.f;
    size_t idx = (size_t)b * Tlen * Dm + d;
    for (int t0 = 0; t0 < Tlen; t0 += 16) {
        float xv[16];
#pragma unroll
        for (int i = 0; i < 16; i++) xv[i] = v[idx + (size_t)i * Dm];
#pragma unroll
        for (int i = 0; i < 16; i++) {
            prev = fmaf(a, xv[i], om * prev);
            xv[i] = prev;
        }
#pragma unroll
        for (int i = 0; i < 16; i++) v[idx + (size_t)i * Dm] = xv[i];
        idx += (size_t)16 * Dm;
    }
}

__global__ __launch_bounds__(256) void silu_k(float* __restrict__ m1,
                                              const float* __restrict__ m2) {
    size_t i0 = (size_t)blockIdx.x * 1024 + threadIdx.x;
#pragma unroll
    for (int i = 0; i < 4; i++) {
        size_t idx = i0 + i * 256;
        float g = m1[idx];
        float s = g / (1.f + expf(-g));
        m1[idx] = to_tf32(s * m2[idx]);
    }
}

__global__ __launch_bounds__(256) void cvt_k(const float* __restrict__ in,
                                             float* __restrict__ out) {
    size_t i = (size_t)blockIdx.x * 256 + threadIdx.x;
    float4 v = ((const float4*)in)[i];
    v.x = to_tf32(v.x); v.y = to_tf32(v.y);
    v.z = to_tf32(v.z); v.w = to_tf32(v.w);
    ((float4*)out)[i] = v;
}

// ================= delta-rule scan v2 =================
// grid (Dm/32, Bb), 256 threads = 8 warps. Warp w owns rows rowbase+4w..4w+3.
// Lane l owns column pairs {64j+2l, 64j+2l+1}, j=0..15 (f32x2 packed).
// Per step: loop1 computes d_r = S_r.k, os_r = S_r.q, kq = k.q (k kept in regs);
// one fused 9-scalar butterfly; o_r = os_r + e_r*kq; loop2 updates S only.
__global__ __launch_bounds__(256, 1) void delta_k(const float* __restrict__ q,
                                                  const float* __restrict__ k,
                                                  const float* __restrict__ v,
                                                  const float* __restrict__ beta,
                                                  float* __restrict__ o) {
    __shared__ __align__(16) float ksm[2][Dm];
    __shared__ __align__(16) float qsm[2][Dm];
    __shared__ __align__(16) float vsm[2][32];
    __shared__ float bsm[2];

    int b = blockIdx.y;
    int rowbase = blockIdx.x * 32;
    int tid = threadIdx.x;
    int lane = tid & 31, w = tid >> 5;   // 8 warps

    const float* qb = q + (size_t)b * Tlen * Dm;
    const float* kb = k + (size_t)b * Tlen * Dm;
    const float* vb = v + (size_t)b * Tlen * Dm;
    const float* betab = beta + (size_t)b * Tlen;
    float* ob = o + (size_t)b * Tlen * Dm;

    ull S0[16], S1[16], S2[16], S3[16];
#pragma unroll
    for (int j = 0; j < 16; j++) { S0[j] = 0ull; S1[j] = 0ull; S2[j] = 0ull; S3[j] = 0ull; }

    // stage t=0 (float4: 256 thr x 16B = 4KB)
    ((float4*)ksm[0])[tid] = ((const float4*)kb)[tid];
    ((float4*)qsm[0])[tid] = ((const float4*)qb)[tid];
    if (tid < 8) ((float4*)vsm[0])[tid] = ((const float4*)(vb + rowbase))[tid];
    if (tid == 0) bsm[0] = betab[0];
    __syncthreads();

    for (int t = 0; t < Tlen; t++) {
        int p = t & 1;
        if (t + 1 < Tlen) {
            size_t nb = (size_t)(t + 1) * Dm;
            ((float4*)ksm[p ^ 1])[tid] = ((const float4*)(kb + nb))[tid];
            ((float4*)qsm[p ^ 1])[tid] = ((const float4*)(qb + nb))[tid];
            if (tid < 8)
                ((float4*)vsm[p ^ 1])[tid] = ((const float4*)(vb + nb + rowbase))[tid];
            if (tid == 0) bsm[p ^ 1] = betab[t + 1];
        }

        const float* kp = ksm[p];
        const float* qp = qsm[p];

        ull kk[16];
        ull d0 = 0, d1 = 0, d2 = 0, d3 = 0;
        ull s0 = 0, s1 = 0, s2 = 0, s3 = 0;
        ull kqp = 0;
#pragma unroll
        for (int j = 0; j < 16; j++) {
            kk[j] = *reinterpret_cast<const ull*>(&kp[j * 64 + 2 * lane]);
            ull qq = *reinterpret_cast<const ull*>(&qp[j * 64 + 2 * lane]);
            FMA2(d0, S0[j], kk[j], d0);
            FMA2(d1, S1[j], kk[j], d1);
            FMA2(d2, S2[j], kk[j], d2);
            FMA2(d3, S3[j], kk[j], d3);
            FMA2(s0, S0[j], qq, s0);
            FMA2(s1, S1[j], qq, s1);
            FMA2(s2, S2[j], qq, s2);
            FMA2(s3, S3[j], qq, s3);
            FMA2(kqp, kk[j], qq, kqp);
        }
        float dv0 = hsum2(d0), dv1 = hsum2(d1), dv2 = hsum2(d2), dv3 = hsum2(d3);
        float sv0 = hsum2(s0), sv1 = hsum2(s1), sv2 = hsum2(s2), sv3 = hsum2(s3);
        float kq = hsum2(kqp);
#pragma unroll
        for (int off = 16; off; off >>= 1) {
            dv0 += __shfl_xor_sync(0xffffffffu, dv0, off);
            dv1 += __shfl_xor_sync(0xffffffffu, dv1, off);
            dv2 += __shfl_xor_sync(0xffffffffu, dv2, off);
            dv3 += __shfl_xor_sync(0xffffffffu, dv3, off);
            sv0 += __shfl_xor_sync(0xffffffffu, sv0, off);
            sv1 += __shfl_xor_sync(0xffffffffu, sv1, off);
            sv2 += __shfl_xor_sync(0xffffffffu, sv2, off);
            sv3 += __shfl_xor_sync(0xffffffffu, sv3, off);
            kq  += __shfl_xor_sync(0xffffffffu, kq, off);
        }
        float bt = bsm[p];
        const float* vp = vsm[p] + 4 * w;
        float e0 = bt * (vp[0] - dv0);
        float e1 = bt * (vp[1] - dv1);
        float e2 = bt * (vp[2] - dv2);
        float e3 = bt * (vp[3] - dv3);
        // outputs: o_r = sv_r + e_r * kq
        if (lane < 4) {
            float oe = (lane & 2) ? ((lane & 1) ? e3 : e2) : ((lane & 1) ? e1 : e0);
            float osv = (lane & 2) ? ((lane & 1) ? sv3 : sv2) : ((lane & 1) ? sv1 : sv0);
            ob[(size_t)t * Dm + rowbase + 4 * w + lane] = to_tf32(fmaf(oe, kq, osv));
        }
        ull e0p = pk2(e0, e0), e1p = pk2(e1, e1), e2p = pk2(e2, e2), e3p = pk2(e3, e3);
#pragma unroll
        for (int j = 0; j < 16; j++) {
            FMA2(S0[j], e0p, kk[j], S0[j]);
            FMA2(S1[j], e1p, kk[j], S1[j]);
            FMA2(S2[j], e2p, kk[j], S2[j]);
            FMA2(S3[j], e3p, kk[j], S3[j]);
        }
        __syncthreads();
    }
}

// ================= tf32 tensor-core GEMM, cp.async 3-stage =================
#define AST 20
#define BSTR 136
#define STAGES 3

template <int EPI>
__global__ __launch_bounds__(256, 2) void tgemm(const float* __restrict__ A,
                                                const float* __restrict__ B,
                                                float* __restrict__ C,
                                                const float* __restrict__ Res,
                                                int M, int N, int K) {
    __shared__ __align__(16) float As[STAGES][128 * AST];
    __shared__ __align__(16) float Bs[STAGES][16 * BSTR];

    const int tid = threadIdx.x;
    const int lane = tid & 31, wid = tid >> 5;
    const int warp_m = wid & 1, warp_n = wid >> 1;
    const int gid = lane >> 2, tig = lane & 3;
    const int bm = blockIdx.y, bn = blockIdx.x;

    float4 acc[4][4];
#pragma unroll
    for (int i = 0; i < 4; i++)
#pragma unroll
        for (int j = 0; j < 4; j++) acc[i][j] = make_float4(0.f, 0.f, 0.f, 0.f);

    const float* Ag = A + (size_t)(bm * 128) * K;
    const float* Bg = B + (size_t)bn * 128;

    const int ca0 = tid * 2;
    const int a_r0 = ca0 >> 2, a_cc0 = (ca0 & 3) * 4;
    const int a_r1 = (ca0 + 1) >> 2, a_cc1 = ((ca0 + 1) & 3) * 4;
    const int b_r0 = ca0 >> 5, b_cc0 = (ca0 & 31) * 4;
    const int b_r1 = (ca0 + 1) >> 5, b_cc1 = ((ca0 + 1) & 31) * 4;

    const int ktiles = K >> 4;

    auto issue = [&](int st, int kt) {
        float* as = As[st];
        float* bs = Bs[st];
        const float* ag = Ag + kt * 16;
        const float* bg = Bg + (size_t)(kt * 16) * N;
        cpa16(as + a_r0 * AST + a_cc0, ag + (size_t)a_r0 * K + a_cc0);
        cpa16(as + a_r1 * AST + a_cc1, ag + (size_t)a_r1 * K + a_cc1);
        cpa16(bs + b_r0 * BSTR + b_cc0, bg + (size_t)b_r0 * N + b_cc0);
        cpa16(bs + b_r1 * BSTR + b_cc1, bg + (size_t)b_r1 * N + b_cc1);
    };

#pragma unroll
    for (int s = 0; s < STAGES - 1; s++) {
        issue(s, s);
        CP_COMMIT();
    }

    int st = 0;
    for (int kt = 0; kt < ktiles; kt++) {
        CP_WAIT(STAGES - 2);
        __syncthreads();
        int nk = kt + STAGES - 1;
        if (nk < ktiles) issue((st + STAGES - 1) % STAGES, nk);
        CP_COMMIT();

        const float* as = As[st];
        const float* bs = Bs[st];
#pragma unroll
        for (int s = 0; s < 2; s++) {
            float a0[4], a1[4], a2[4], a3[4];
#pragma unroll
            for (int mt = 0; mt < 4; mt++) {
                const float* ap = as + (warp_m * 64 + mt * 16 + gid) * AST + 8 * s + tig;
                a0[mt] = ap[0];
                a2[mt] = ap[4];
                a1[mt] = ap[8 * AST];
                a3[mt] = ap[8 * AST + 4];
            }
#pragma unroll
            for (int nt = 0; nt < 4; nt++) {
                int cn = warp_n * 32 + nt * 8 + gid;
                float b0 = bs[(8 * s + tig) * BSTR + cn];
                float b1 = bs[(8 * s + tig + 4) * BSTR + cn];
#pragma unroll
                for (int mt = 0; mt < 4; mt++) {
                    mma_tf32(acc[mt][nt],
                             __float_as_uint(a0[mt]), __float_as_uint(a1[mt]),
                             __float_as_uint(a2[mt]), __float_as_uint(a3[mt]),
                             __float_as_uint(b0), __float_as_uint(b1));
                }
            }
        }
        st = (st + 1) % STAGES;
    }

#pragma unroll
    for (int mt = 0; mt < 4; mt++) {
        size_t r0 = (size_t)(bm * 128 + warp_m * 64 + mt * 16 + gid);
#pragma unroll
        for (int nt = 0; nt < 4; nt++) {
            size_t cg = (size_t)(bn * 128 + warp_n * 32 + nt * 8 + 2 * tig);
            size_t i0 = r0 * N + cg;
            size_t i1 = (r0 + 8) * N + cg;
            float2 v0 = make_float2(acc[mt][nt].x, acc[mt][nt].y);
            float2 v1 = make_float2(acc[mt][nt].z, acc[mt][nt].w);
            if (EPI == 1) {
                float2 x0 = *(const float2*)&Res[i0];
                float2 x1 = *(const float2*)&Res[i1];
                v0.x += x0.x; v0.y += x0.y; v1.x += x1.x; v1.y += x1.y;
            }
            if (EPI == 2) {
                float2 x0 = *(const float2*)&C[i0];
                float2 x1 = *(const float2*)&C[i1];
                v0.x += x0.x; v0.y += x0.y; v1.x += x1.x; v1.y += x1.y;
            }
            *(float2*)&C[i0] = v0;
            *(float2*)&C[i1] = v1;
        }
    }
}

// ================= launch =================
extern "C" void kernel_launch(void* const* d_in, const int* in_sizes, int n_in,
                              void* d_out, int out_size) {
    const float* x   = (const float*)d_in[0];
    const float* n1w = (const float*)d_in[1];
    const float* Wq  = (const float*)d_in[2];
    const float* Wk  = (const float*)d_in[3];
    const float* Wv  = (const float*)d_in[4];
    const float* bw  = (const float*)d_in[5];
    const float* bbp = (const float*)d_in[6];
    const float* Wo  = (const float*)d_in[7];
    const float* al  = (const float*)d_in[8];
    const float* n2w = (const float*)d_in[9];
    const float* wg  = (const float*)d_in[10];
    const float* wu  = (const float*)d_in[11];
    const float* wd  = (const float*)d_in[12];
    float* out = (float*)d_out;

    float *h, *q, *k, *v, *beta, *m1, *m2, *wt;
    cudaGetSymbolAddress((void**)&h,    g_h);
    cudaGetSymbolAddress((void**)&q,    g_q);
    cudaGetSymbolAddress((void**)&k,    g_k);
    cudaGetSymbolAddress((void**)&v,    g_v);
    cudaGetSymbolAddress((void**)&beta, g_beta);
    cudaGetSymbolAddress((void**)&m1,   g_m1);
    cudaGetSymbolAddress((void**)&m2,   g_m2);
    cudaGetSymbolAddress((void**)&wt,   g_wt);

    float* cWq = wt;
    float* cWk = wt + 1024 * 1024;
    float* cWv = wt + 2 * 1024 * 1024;
    float* cWo = wt + 3 * 1024 * 1024;
    float* cWg = wt + 4 * 1024 * 1024;
    float* cWu = wt + 6 * 1024 * 1024;
    float* cWd = wt + 8 * 1024 * 1024;

    cvt_k<<<1024, 256>>>(Wq, cWq);
    cvt_k<<<1024, 256>>>(Wk, cWk);
    cvt_k<<<1024, 256>>>(Wv, cWv);
    cvt_k<<<1024, 256>>>(Wo, cWo);
    cvt_k<<<2048, 256>>>(wg, cWg);
    cvt_k<<<2048, 256>>>(wu, cWu);
    cvt_k<<<2048, 256>>>(wd, cWd);

    rmsnorm_k<true><<<BT, 256>>>(x, n1w, h);

    tgemm<0><<<dim3(Dm / 128, BT / 128), 256>>>(h, cWq, q, nullptr, BT, Dm, Dm);
    tgemm<0><<<dim3(Dm / 128, BT / 128), 256>>>(h, cWk, k, nullptr, BT, Dm, Dm);
    tgemm<0><<<dim3(Dm / 128, BT / 128), 256>>>(h, cWv, v, nullptr, BT, Dm, Dm);

    beta_k<<<BT / 8, 256>>>(h, bw, bbp, beta);
    knorm_k<<<BT, 256>>>(k);
    ema_k<<<dim3(Dm / 256, Bb), 256>>>(v, al);

    delta_k<<<dim3(Dm / 32, Bb), 256>>>(q, k, v, beta, h);

    tgemm<1><<<dim3(Dm / 128, BT / 128), 256>>>(h, cWo, out, x, BT, Dm, Dm);
    rmsnorm_k<true><<<BT, 256>>>(out, n2w, q);

    tgemm<0><<<dim3(HIDm / 128, BT / 128), 256>>>(q, cWg, m1, nullptr, BT, HIDm, Dm);
    tgemm<0><<<dim3(HIDm / 128, BT / 128), 256>>>(q, cWu, m2, nullptr, BT, HIDm, Dm);
    silu_k<<<(BT * HIDm) / 1024, 256>>>(m1, m2);
    tgemm<2><<<dim3(Dm / 128, BT / 128), 256>>>(m1, cWd, out, nullptr, BT, Dm, HIDm);
}

// round 14
// speedup vs baseline: 1.7984x; 1.0015x over previous
#include <cuda_runtime.h>
#include <math.h>
#include <stdint.h>

#define BT   8192
#define Dm   1024
#define HIDm 2048
#define Tlen 2048
#define Bb   4
#define QKS  3072   // fused qkv row stride
#define GUS  4096   // fused gate/up row stride

typedef unsigned long long ull;

// ---- static scratch ----
__device__ float g_h[BT * Dm];            // h, then attn_out, then h2
__device__ float g_qkv[BT * QKS];         // fused q|k|v
__device__ float g_beta[BT];
__device__ float g_mgu[BT * GUS];         // fused gate|up, silu in-place
__device__ float g_wt[10 * 1024 * 1024];  // Bqkv 3M | Bgu 4M | cWo 1M | cWd 2M

// ================= helpers =================
__device__ __forceinline__ float to_tf32(float x) {
    float r;
    asm("cvt.rna.tf32.f32 %0, %1;" : "=f"(r) : "f"(x));
    return r;
}
__device__ __forceinline__ void mma_tf32(float4& c, uint32_t a0, uint32_t a1,
                                         uint32_t a2, uint32_t a3,
                                         uint32_t b0, uint32_t b1) {
    asm volatile(
        "mma.sync.aligned.m16n8k8.row.col.f32.tf32.tf32.f32 "
        "{%0,%1,%2,%3}, {%4,%5,%6,%7}, {%8,%9}, {%0,%1,%2,%3};"
        : "+f"(c.x), "+f"(c.y), "+f"(c.z), "+f"(c.w)
        : "r"(a0), "r"(a1), "r"(a2), "r"(a3), "r"(b0), "r"(b1));
}
__device__ __forceinline__ void cpa16(void* smem, const void* gmem) {
    uint32_t sa = (uint32_t)__cvta_generic_to_shared(smem);
    asm volatile("cp.async.ca.shared.global [%0], [%1], 16;" :: "r"(sa), "l"(gmem));
}
#define CP_COMMIT() asm volatile("cp.async.commit_group;")
#define CP_WAIT(n)  asm volatile("cp.async.wait_group %0;" :: "n"(n))

__device__ __forceinline__ ull pk2(float a, float b) {
    ull r;
    asm("mov.b64 %0, {%1,%2};" : "=l"(r) : "f"(a), "f"(b));
    return r;
}
__device__ __forceinline__ float2 unpk2(ull v) {
    float2 f;
    asm("mov.b64 {%0,%1}, %2;" : "=f"(f.x), "=f"(f.y) : "l"(v));
    return f;
}
__device__ __forceinline__ float hsum2(ull v) {
    float2 f = unpk2(v);
    return f.x + f.y;
}
#define FMA2(d, a, b, c) asm("fma.rn.f32x2 %0, %1, %2, %3;" : "=l"(d) : "l"(a), "l"(b), "l"(c))

__device__ __forceinline__ float block_sum_256(float v) {
    __shared__ float sh[8];
    int lane = threadIdx.x & 31, wid = threadIdx.x >> 5;
#pragma unroll
    for (int o = 16; o; o >>= 1) v += __shfl_xor_sync(0xffffffffu, v, o);
    if (lane == 0) sh[wid] = v;
    __syncthreads();
    if (wid == 0) {
        float t = (lane < 8) ? sh[lane] : 0.f;
#pragma unroll
        for (int o = 4; o; o >>= 1) t += __shfl_xor_sync(0xffffffffu, t, o);
        if (lane == 0) sh[0] = t;
    }
    __syncthreads();
    return sh[0];
}

// ================= small kernels =================
template <bool CVT>
__global__ __launch_bounds__(256) void rmsnorm_k(const float* __restrict__ x,
                                                 const float* __restrict__ w,
                                                 float* __restrict__ out) {
    int row = blockIdx.x;
    const float* xr = x + (size_t)row * Dm;
    float* orow = out + (size_t)row * Dm;
    float v[4];
    float ss = 0.f;
#pragma unroll
    for (int i = 0; i < 4; i++) {
        v[i] = xr[i * 256 + threadIdx.x];
        ss += v[i] * v[i];
    }
    float tot = block_sum_256(ss);
    float scale = rsqrtf(tot * (1.0f / Dm) + 1e-6f);
#pragma unroll
    for (int i = 0; i < 4; i++) {
        int c = i * 256 + threadIdx.x;
        float r = v[i] * scale * w[c];
        orow[c] = CVT ? to_tf32(r) : r;
    }
}

// k-normalize inside fused qkv (k section at +Dm, row stride QKS)
__global__ __launch_bounds__(256) void knorm_k(float* __restrict__ qkv) {
    int row = blockIdx.x;
    float* kr = qkv + (size_t)row * QKS + Dm;
    float v[4];
    float ss = 0.f;
#pragma unroll
    for (int i = 0; i < 4; i++) {
        v[i] = kr[i * 256 + threadIdx.x];
        ss += v[i] * v[i];
    }
    float tot = block_sum_256(ss);
    float scale = 1.f / fmaxf(sqrtf(tot), 1e-12f);
#pragma unroll
    for (int i = 0; i < 4; i++) kr[i * 256 + threadIdx.x] = v[i] * scale;
}

__global__ __launch_bounds__(256) void beta_k(const float* __restrict__ h,
                                              const float* __restrict__ bw,
                                              const float* __restrict__ bb,
                                              float* __restrict__ beta) {
    int row = blockIdx.x * 8 + (threadIdx.x >> 5);
    int lane = threadIdx.x & 31;
    const float* hr = h + (size_t)row * Dm;
    float s = 0.f;
#pragma unroll
    for (int m = 0; m < 32; m++) s += hr[m * 32 + lane] * bw[m * 32 + lane];
#pragma unroll
    for (int o = 16; o; o >>= 1) s += __shfl_xor_sync(0xffffffffu, s, o);
    if (lane == 0) beta[row] = 1.f / (1.f + expf(-(s + bb[0])));
}

// EMA over v section of fused qkv (at +2*Dm, row stride QKS), MLP=16
__global__ __launch_bounds__(256) void ema_k(float* __restrict__ qkv,
                                             const float* __restrict__ alpha_logit) {
    int d = blockIdx.x * 256 + threadIdx.x;
    int b = blockIdx.y;
    float a = 1.f / (1.f + expf(-alpha_logit[d]));
    float om = 1.f - a;
    float prev = 0.f;
    size_t idx = (size_t)b * Tlen * QKS + 2 * Dm + d;
    for (int t0 = 0; t0 < Tlen; t0 += 16) {
        float xv[16];
#pragma unroll
        for (int i = 0; i < 16; i++) xv[i] = qkv[idx + (size_t)i * QKS];
#pragma unroll
        for (int i = 0; i < 16; i++) {
            prev = fmaf(a, xv[i], om * prev);
            xv[i] = prev;
        }
#pragma unroll
        for (int i = 0; i < 16; i++) qkv[idx + (size_t)i * QKS] = xv[i];
        idx += (size_t)16 * QKS;
    }
}

// silu(gate)*up in place into gate half of fused mgu (row stride GUS)
__global__ __launch_bounds__(256) void silu_k(float* __restrict__ mgu) {
    size_t i0 = (size_t)blockIdx.x * 1024 + threadIdx.x;
#pragma unroll
    for (int i = 0; i < 4; i++) {
        size_t idx = i0 + i * 256;               // logical [BT][2048]
        size_t row = idx >> 11, c = idx & 2047;
        size_t a = (row << 12) + c;              // gate addr
        float g = mgu[a];
        float u = mgu[a + 2048];
        float s = g / (1.f + expf(-g));
        mgu[a] = to_tf32(s * u);
    }
}

// concat-convert 3 [1024,1024] weights -> Bqkv[1024][3072], tf32
__global__ __launch_bounds__(256) void cvt_cat3(const float* __restrict__ w0,
                                                const float* __restrict__ w1,
                                                const float* __restrict__ w2,
                                                float* __restrict__ out) {
    int j = blockIdx.y;
    const float* in = (j == 0) ? w0 : (j == 1) ? w1 : w2;
    size_t i = (size_t)blockIdx.x * 256 + threadIdx.x;   // float4 index, 1024*256
    size_t k = i >> 8, c4 = i & 255;
    float4 v = ((const float4*)in)[i];
    v.x = to_tf32(v.x); v.y = to_tf32(v.y);
    v.z = to_tf32(v.z); v.w = to_tf32(v.w);
    ((float4*)out)[k * 768 + (size_t)j * 256 + c4] = v;
}

// concat-convert 2 [1024,2048] weights -> Bgu[1024][4096], tf32
__global__ __launch_bounds__(256) void cvt_cat2(const float* __restrict__ w0,
                                                const float* __restrict__ w1,
                                                float* __restrict__ out) {
    int j = blockIdx.y;
    const float* in = (j == 0) ? w0 : w1;
    size_t i = (size_t)blockIdx.x * 256 + threadIdx.x;   // float4 index, 1024*512
    size_t k = i >> 9, c4 = i & 511;
    float4 v = ((const float4*)in)[i];
    v.x = to_tf32(v.x); v.y = to_tf32(v.y);
    v.z = to_tf32(v.z); v.w = to_tf32(v.w);
    ((float4*)out)[k * 1024 + (size_t)j * 512 + c4] = v;
}

__global__ __launch_bounds__(256) void cvt_k(const float* __restrict__ in,
                                             float* __restrict__ out) {
    size_t i = (size_t)blockIdx.x * 256 + threadIdx.x;
    float4 v = ((const float4*)in)[i];
    v.x = to_tf32(v.x); v.y = to_tf32(v.y);
    v.z = to_tf32(v.z); v.w = to_tf32(v.w);
    ((float4*)out)[i] = v;
}

// ================= delta-rule scan v2 (fused qkv input) =================
// grid (Dm/32, Bb), 256 threads = 8 warps. Warp w owns rows rowbase+4w..4w+3.
__global__ __launch_bounds__(256, 1) void delta_k(const float* __restrict__ qkv,
                                                  const float* __restrict__ beta,
                                                  float* __restrict__ o) {
    __shared__ __align__(16) float ksm[2][Dm];
    __shared__ __align__(16) float qsm[2][Dm];
    __shared__ __align__(16) float vsm[2][32];
    __shared__ float bsm[2];

    int b = blockIdx.y;
    int rowbase = blockIdx.x * 32;
    int tid = threadIdx.x;
    int lane = tid & 31, w = tid >> 5;

    const float* qb = qkv + (size_t)b * Tlen * QKS;
    const float* kb = qb + Dm;
    const float* vb = qb + 2 * Dm;
    const float* betab = beta + (size_t)b * Tlen;
    float* ob = o + (size_t)b * Tlen * Dm;

    ull S0[16], S1[16], S2[16], S3[16];
#pragma unroll
    for (int j = 0; j < 16; j++) { S0[j] = 0ull; S1[j] = 0ull; S2[j] = 0ull; S3[j] = 0ull; }

    ((float4*)ksm[0])[tid] = ((const float4*)kb)[tid];
    ((float4*)qsm[0])[tid] = ((const float4*)qb)[tid];
    if (tid < 8) ((float4*)vsm[0])[tid] = ((const float4*)(vb + rowbase))[tid];
    if (tid == 0) bsm[0] = betab[0];
    __syncthreads();

    for (int t = 0; t < Tlen; t++) {
        int p = t & 1;
        if (t + 1 < Tlen) {
            size_t nb = (size_t)(t + 1) * QKS;
            ((float4*)ksm[p ^ 1])[tid] = ((const float4*)(kb + nb))[tid];
            ((float4*)qsm[p ^ 1])[tid] = ((const float4*)(qb + nb))[tid];
            if (tid < 8)
                ((float4*)vsm[p ^ 1])[tid] = ((const float4*)(vb + nb + rowbase))[tid];
            if (tid == 0) bsm[p ^ 1] = betab[t + 1];
        }

        const float* kp = ksm[p];
        const float* qp = qsm[p];

        ull kk[16];
        ull d0 = 0, d1 = 0, d2 = 0, d3 = 0;
        ull s0 = 0, s1 = 0, s2 = 0, s3 = 0;
        ull kqp = 0;
#pragma unroll
        for (int j = 0; j < 16; j++) {
            kk[j] = *reinterpret_cast<const ull*>(&kp[j * 64 + 2 * lane]);
            ull qq = *reinterpret_cast<const ull*>(&qp[j * 64 + 2 * lane]);
            FMA2(d0, S0[j], kk[j], d0);
            FMA2(d1, S1[j], kk[j], d1);
            FMA2(d2, S2[j], kk[j], d2);
            FMA2(d3, S3[j], kk[j], d3);
            FMA2(s0, S0[j], qq, s0);
            FMA2(s1, S1[j], qq, s1);
            FMA2(s2, S2[j], qq, s2);
            FMA2(s3, S3[j], qq, s3);
            FMA2(kqp, kk[j], qq, kqp);
        }
        float dv0 = hsum2(d0), dv1 = hsum2(d1), dv2 = hsum2(d2), dv3 = hsum2(d3);
        float sv0 = hsum2(s0), sv1 = hsum2(s1), sv2 = hsum2(s2), sv3 = hsum2(s3);
        float kq = hsum2(kqp);
#pragma unroll
        for (int off = 16; off; off >>= 1) {
            dv0 += __shfl_xor_sync(0xffffffffu, dv0, off);
            dv1 += __shfl_xor_sync(0xffffffffu, dv1, off);
            dv2 += __shfl_xor_sync(0xffffffffu, dv2, off);
            dv3 += __shfl_xor_sync(0xffffffffu, dv3, off);
            sv0 += __shfl_xor_sync(0xffffffffu, sv0, off);
            sv1 += __shfl_xor_sync(0xffffffffu, sv1, off);
            sv2 += __shfl_xor_sync(0xffffffffu, sv2, off);
            sv3 += __shfl_xor_sync(0xffffffffu, sv3, off);
            kq  += __shfl_xor_sync(0xffffffffu, kq, off);
        }
        float bt = bsm[p];
        const float* vp = vsm[p] + 4 * w;
        float e0 = bt * (vp[0] - dv0);
        float e1 = bt * (vp[1] - dv1);
        float e2 = bt * (vp[2] - dv2);
        float e3 = bt * (vp[3] - dv3);
        if (lane < 4) {
            float oe = (lane & 2) ? ((lane & 1) ? e3 : e2) : ((lane & 1) ? e1 : e0);
            float osv = (lane & 2) ? ((lane & 1) ? sv3 : sv2) : ((lane & 1) ? sv1 : sv0);
            ob[(size_t)t * Dm + rowbase + 4 * w + lane] = to_tf32(fmaf(oe, kq, osv));
        }
        ull e0p = pk2(e0, e0), e1p = pk2(e1, e1), e2p = pk2(e2, e2), e3p = pk2(e3, e3);
#pragma unroll
        for (int j = 0; j < 16; j++) {
            FMA2(S0[j], e0p, kk[j], S0[j]);
            FMA2(S1[j], e1p, kk[j], S1[j]);
            FMA2(S2[j], e2p, kk[j], S2[j]);
            FMA2(S3[j], e3p, kk[j], S3[j]);
        }
        __syncthreads();
    }
}

// ================= tf32 tensor-core GEMM, cp.async 3-stage, strided A =================
#define AST 20
#define BSTR 136
#define STAGES 3

template <int EPI>
__global__ __launch_bounds__(256, 2) void tgemm(const float* __restrict__ A,
                                                const float* __restrict__ B,
                                                float* __restrict__ C,
                                                const float* __restrict__ Res,
                                                int M, int N, int K, int lda) {
    __shared__ __align__(16) float As[STAGES][128 * AST];
    __shared__ __align__(16) float Bs[STAGES][16 * BSTR];

    const int tid = threadIdx.x;
    const int lane = tid & 31, wid = tid >> 5;
    const int warp_m = wid & 1, warp_n = wid >> 1;
    const int gid = lane >> 2, tig = lane & 3;
    const int bm = blockIdx.y, bn = blockIdx.x;

    float4 acc[4][4];
#pragma unroll
    for (int i = 0; i < 4; i++)
#pragma unroll
        for (int j = 0; j < 4; j++) acc[i][j] = make_float4(0.f, 0.f, 0.f, 0.f);

    const float* Ag = A + (size_t)(bm * 128) * lda;
    const float* Bg = B + (size_t)bn * 128;

    const int ca0 = tid * 2;
    const int a_r0 = ca0 >> 2, a_cc0 = (ca0 & 3) * 4;
    const int a_r1 = (ca0 + 1) >> 2, a_cc1 = ((ca0 + 1) & 3) * 4;
    const int b_r0 = ca0 >> 5, b_cc0 = (ca0 & 31) * 4;
    const int b_r1 = (ca0 + 1) >> 5, b_cc1 = ((ca0 + 1) & 31) * 4;

    const int ktiles = K >> 4;

    auto issue = [&](int st, int kt) {
        float* as = As[st];
        float* bs = Bs[st];
        const float* ag = Ag + kt * 16;
        const float* bg = Bg + (size_t)(kt * 16) * N;
        cpa16(as + a_r0 * AST + a_cc0, ag + (size_t)a_r0 * lda + a_cc0);
        cpa16(as + a_r1 * AST + a_cc1, ag + (size_t)a_r1 * lda + a_cc1);
        cpa16(bs + b_r0 * BSTR + b_cc0, bg + (size_t)b_r0 * N + b_cc0);
        cpa16(bs + b_r1 * BSTR + b_cc1, bg + (size_t)b_r1 * N + b_cc1);
    };

#pragma unroll
    for (int s = 0; s < STAGES - 1; s++) {
        issue(s, s);
        CP_COMMIT();
    }

    int st = 0;
    for (int kt = 0; kt < ktiles; kt++) {
        CP_WAIT(STAGES - 2);
        __syncthreads();
        int nk = kt + STAGES - 1;
        if (nk < ktiles) issue((st + STAGES - 1) % STAGES, nk);
        CP_COMMIT();

        const float* as = As[st];
        const float* bs = Bs[st];
#pragma unroll
        for (int s = 0; s < 2; s++) {
            float a0[4], a1[4], a2[4], a3[4];
#pragma unroll
            for (int mt = 0; mt < 4; mt++) {
                const float* ap = as + (warp_m * 64 + mt * 16 + gid) * AST + 8 * s + tig;
                a0[mt] = ap[0];
                a2[mt] = ap[4];
                a1[mt] = ap[8 * AST];
                a3[mt] = ap[8 * AST + 4];
            }
#pragma unroll
            for (int nt = 0; nt < 4; nt++) {
                int cn = warp_n * 32 + nt * 8 + gid;
                float b0 = bs[(8 * s + tig) * BSTR + cn];
                float b1 = bs[(8 * s + tig + 4) * BSTR + cn];
#pragma unroll
                for (int mt = 0; mt < 4; mt++) {
                    mma_tf32(acc[mt][nt],
                             __float_as_uint(a0[mt]), __float_as_uint(a1[mt]),
                             __float_as_uint(a2[mt]), __float_as_uint(a3[mt]),
                             __float_as_uint(b0), __float_as_uint(b1));
                }
            }
        }
        st = (st + 1) % STAGES;
    }

#pragma unroll
    for (int mt = 0; mt < 4; mt++) {
        size_t r0 = (size_t)(bm * 128 + warp_m * 64 + mt * 16 + gid);
#pragma unroll
        for (int nt = 0; nt < 4; nt++) {
            size_t cg = (size_t)(bn * 128 + warp_n * 32 + nt * 8 + 2 * tig);
            size_t i0 = r0 * N + cg;
            size_t i1 = (r0 + 8) * N + cg;
            float2 v0 = make_float2(acc[mt][nt].x, acc[mt][nt].y);
            float2 v1 = make_float2(acc[mt][nt].z, acc[mt][nt].w);
            if (EPI == 1) {
                float2 x0 = *(const float2*)&Res[i0];
                float2 x1 = *(const float2*)&Res[i1];
                v0.x += x0.x; v0.y += x0.y; v1.x += x1.x; v1.y += x1.y;
            }
            if (EPI == 2) {
                float2 x0 = *(const float2*)&C[i0];
                float2 x1 = *(const float2*)&C[i1];
                v0.x += x0.x; v0.y += x0.y; v1.x += x1.x; v1.y += x1.y;
            }
            *(float2*)&C[i0] = v0;
            *(float2*)&C[i1] = v1;
        }
    }
}

// ================= launch =================
extern "C" void kernel_launch(void* const* d_in, const int* in_sizes, int n_in,
                              void* d_out, int out_size) {
    const float* x   = (const float*)d_in[0];
    const float* n1w = (const float*)d_in[1];
    const float* Wq  = (const float*)d_in[2];
    const float* Wk  = (const float*)d_in[3];
    const float* Wv  = (const float*)d_in[4];
    const float* bw  = (const float*)d_in[5];
    const float* bbp = (const float*)d_in[6];
    const float* Wo  = (const float*)d_in[7];
    const float* al  = (const float*)d_in[8];
    const float* n2w = (const float*)d_in[9];
    const float* wg  = (const float*)d_in[10];
    const float* wu  = (const float*)d_in[11];
    const float* wd  = (const float*)d_in[12];
    float* out = (float*)d_out;

    float *h, *qkv, *beta, *mgu, *wt;
    cudaGetSymbolAddress((void**)&h,    g_h);
    cudaGetSymbolAddress((void**)&qkv,  g_qkv);
    cudaGetSymbolAddress((void**)&beta, g_beta);
    cudaGetSymbolAddress((void**)&mgu,  g_mgu);
    cudaGetSymbolAddress((void**)&wt,   g_wt);

    float* Bqkv = wt;                      // 3M: [1024][3072]
    float* Bgu  = wt + 3 * 1024 * 1024;    // 4M: [1024][4096]
    float* cWo  = wt + 7 * 1024 * 1024;    // 1M
    float* cWd  = wt + 8 * 1024 * 1024;    // 2M

    // 1-4: weight conversions
    cvt_cat3<<<dim3(1024, 3), 256>>>(Wq, Wk, Wv, Bqkv);
    cvt_cat2<<<dim3(2048, 2), 256>>>(wg, wu, Bgu);
    cvt_k<<<1024, 256>>>(Wo, cWo);
    cvt_k<<<2048, 256>>>(wd, cWd);

    // 5: h = tf32(rmsnorm(x))
    rmsnorm_k<true><<<BT, 256>>>(x, n1w, h);

    // 6: fused QKV gemm (captured by ncu -s 5 -c 1)
    tgemm<0><<<dim3(QKS / 128, BT / 128), 256>>>(h, Bqkv, qkv, nullptr, BT, QKS, Dm, Dm);

    // 7-9: beta, knorm, ema
    beta_k<<<BT / 8, 256>>>(h, bw, bbp, beta);
    knorm_k<<<BT, 256>>>(qkv);
    ema_k<<<dim3(Dm / 256, Bb), 256>>>(qkv, al);

    // 10: delta scan -> attn (reuse h)
    delta_k<<<dim3(Dm / 32, Bb), 256>>>(qkv, beta, h);

    // 11: out = x + attn @ Wo
    tgemm<1><<<dim3(Dm / 128, BT / 128), 256>>>(h, cWo, out, x, BT, Dm, Dm, Dm);

    // 12: h2 = tf32(rmsnorm(out)) (reuse h)
    rmsnorm_k<true><<<BT, 256>>>(out, n2w, h);

    // 13: fused gate|up gemm
    tgemm<0><<<dim3(GUS / 128, BT / 128), 256>>>(h, Bgu, mgu, nullptr, BT, GUS, Dm, Dm);

    // 14: silu in place (gate half)
    silu_k<<<(BT * HIDm) / 1024, 256>>>(mgu);

    // 15: out += silu @ w_down (A strided lda=4096)
    tgemm<2><<<dim3(Dm / 128, BT / 128), 256>>>(mgu, cWd, out, nullptr, BT, Dm, HIDm, GUS);
}